// round 9
// baseline (speedup 1.0000x reference)
#include <cuda_runtime.h>
#include <cuda_bf16.h>
#include <cstdint>

// ---------------- constants ----------------
#define B       256
#define T       32
#define XBC     1152        // 2*24*24
#define XT      (B*XBC)
#define A1      400         // 20*20
#define L1SZ    (B*30*A1)   // 3,072,000
#define L3SZ    (B*30*100)  // 768,000
#define L2SZ    (B*100*36)  // 921,600
#define DW1CH   128         // 2 batches per chunk
#define DW2CH   64          // 4 batches per chunk

#define VTH1    15.0f
#define VTH2    10.0f
#define DEC     0.02f
#define ETA_P   0.004f
#define ETA_M   0.003f

// padded pre2 layout: plane stride 133 (30 planes -> 3990, pad to 4096 slots/batch)
#define PPL     133
#define PRE2SL  4096

// ---------------- persistent device state ----------------
__device__ float g_w1[1500];
__device__ float g_w2[75000];
__device__ float g_v1[L1SZ];
__device__ float g_v2[L2SZ];
__device__ float g_tp1[XT];
__device__ float g_to1[L1SZ];
__device__ float g_pre2p[B*PRE2SL*2];     // interleaved (tp2*ETA_P, z3), padded layout
__device__ float g_to2[L2SZ];
__device__ float g_z2[L1SZ];
__device__ float g_z3[L3SZ];
__device__ float g_pzT[B*36*200];         // [b][k][j] float2 = (z5, -ETA_M*to2)
__device__ float g_liv[B*10];
__device__ float g_lii[B*10];
__device__ float g_dw1p[DW1CH*1500];
__device__ float g_dw2p[(size_t)DW2CH*75000];

// ---------------- init ----------------
__global__ void k_init(const float* __restrict__ w1, const float* __restrict__ w2) {
    int i = blockIdx.x * blockDim.x + threadIdx.x;
    if (i < L1SZ) { g_v1[i] = 0.f; g_to1[i] = 0.f; }
    if (i < L2SZ) { g_v2[i] = 0.f; g_to2[i] = 0.f; }
    if (i < XT)   g_tp1[i] = 0.f;
    if (i < B*PRE2SL*2) g_pre2p[i] = 0.f;
    if (i < B*10) { g_liv[i] = 0.f; g_lii[i] = 0.f; }
    if (i < 1500)  g_w1[i] = w1[i];
    if (i < 75000) g_w2[i] = w2[i];
}

// ---------------- K1: conv1 + IAF + to1 trace + fused pool/tp2(padded,scaled); extra blocks: tp1 ----------------
__global__ void k1_conv1(const float* __restrict__ x, int t) {
    const float* xt = x + (size_t)t * XT;
    int tid = threadIdx.x;
    if (blockIdx.x >= B) {
        int base = (blockIdx.x - B) * 8192;
        #pragma unroll 4
        for (int r = 0; r < 32; r++) {
            int i = base + r * 256 + tid;
            float tt = g_tp1[i];
            g_tp1[i] = tt - DEC * tt + xt[i];
        }
        return;
    }
    int b = blockIdx.x;
    __shared__ float xs[XBC];
    __shared__ float w1T[50 * 32];
    for (int i = tid; i < XBC; i += 256) xs[i] = xt[b * XBC + i];
    for (int i = tid; i < 1600; i += 256) {
        int c = i >> 5, oc = i & 31;
        w1T[i] = (oc < 30) ? g_w1[oc * 50 + c] : 0.f;
    }
    __syncthreads();

    for (int p = tid; p < A1; p += 256) {
        int oh = p / 20, ow = p % 20;
        float patch[50];
        #pragma unroll
        for (int ic = 0; ic < 2; ic++)
            #pragma unroll
            for (int kh = 0; kh < 5; kh++)
                #pragma unroll
                for (int kw = 0; kw < 5; kw++)
                    patch[ic*25 + kh*5 + kw] = xs[ic*576 + (oh+kh)*24 + ow + kw];

        for (int g = 0; g < 8; g++) {
            float a0=0.f, a1=0.f, a2=0.f, a3=0.f;
            #pragma unroll
            for (int c = 0; c < 50; c++) {
                float4 w = *(const float4*)&w1T[c*32 + g*4];
                a0 = fmaf(patch[c], w.x, a0);
                a1 = fmaf(patch[c], w.y, a1);
                a2 = fmaf(patch[c], w.z, a2);
                a3 = fmaf(patch[c], w.w, a3);
            }
            float av[4] = {a0, a1, a2, a3};
            #pragma unroll
            for (int q = 0; q < 4; q++) {
                int oc = g*4 + q;
                if (oc < 30) {
                    int idx = b*12000 + oc*A1 + p;
                    float v = g_v1[idx] + av[q];
                    float z = (v > VTH1) ? 1.f : 0.f;
                    g_v1[idx] = v * (1.f - z);
                    g_z2[idx] = z;
                    float tt = g_to1[idx];
                    g_to1[idx] = tt - DEC * tt + z;
                }
            }
        }
    }
    // fused maxpool 2x2 + z3 + scaled/padded tp2 trace
    __syncthreads();
    for (int e = tid; e < 3000; e += 256) {
        int c = e / 100, q = e % 100;
        int oh = q / 10, ow = q % 10;
        int base = b*12000 + c*A1 + oh*40 + ow*2;
        float m = fmaxf(fmaxf(g_z2[base], g_z2[base+1]),
                        fmaxf(g_z2[base+20], g_z2[base+21]));
        g_z3[b*3000 + e] = m;
        int slot = c*PPL + oh*13 + ow;
        float2* pp = (float2*)&g_pre2p[((size_t)b*PRE2SL + slot)*2];
        float2 o = *pp;
        float s = o.x;
        s = s - DEC*s + ETA_P*m;
        float2 nv; nv.x = s; nv.y = m;
        *pp = nv;
    }
}

// ---------------- K3: conv2 (x10) + IAF + to2 trace + pzT + z6 + FC/LI readout ----------------
__global__ void k3_conv2(const float* __restrict__ fc1w, const float* __restrict__ fc1b,
                         const float* __restrict__ outw, float* __restrict__ out, int t) {
    __shared__ float z3s[3000];
    __shared__ float w2s[7500];
    int b = blockIdx.x, tid = threadIdx.x;
    for (int i = tid; i < 3000; i += 600) z3s[i] = g_z3[b*3000 + i];

    int oc = tid % 100, ohh = tid / 100;
    float acc[6] = {0.f,0.f,0.f,0.f,0.f,0.f};

    for (int ic0 = 0; ic0 < 30; ic0 += 3) {
        __syncthreads();
        for (int i = tid; i < 7500; i += 600) {
            int o2 = i / 75, cc = i % 75;
            w2s[i] = g_w2[o2*750 + ic0*25 + cc];
        }
        __syncthreads();
        #pragma unroll
        for (int icl = 0; icl < 3; icl++) {
            const float* zb = &z3s[(ic0 + icl)*100];
            const float* wb = &w2s[oc*75 + icl*25];
            #pragma unroll
            for (int kh = 0; kh < 5; kh++) {
                float r[10];
                const float* zrow = &zb[(ohh + kh)*10];
                #pragma unroll
                for (int u = 0; u < 5; u++) {
                    float2 v = *(const float2*)&zrow[2*u];
                    r[2*u] = v.x; r[2*u+1] = v.y;
                }
                #pragma unroll
                for (int kw = 0; kw < 5; kw++) {
                    float w = wb[kh*5 + kw];
                    #pragma unroll
                    for (int ow = 0; ow < 6; ow++)
                        acc[ow] = fmaf(w, r[ow + kw], acc[ow]);
                }
            }
        }
    }
    // IAF epilogue
    float zmax = 0.f;
    int obase = b*3600 + oc*36 + ohh*6;
    #pragma unroll
    for (int ow = 0; ow < 6; ow++) {
        int idx = obase + ow;
        float v = g_v2[idx] + 10.0f * acc[ow];
        float z = (v > VTH2) ? 1.f : 0.f;
        g_v2[idx] = v * (1.f - z);
        float tt = g_to2[idx];
        float to2n = tt - DEC * tt + z;
        g_to2[idx] = to2n;
        int k = ohh*6 + ow;
        float2 pv; pv.x = z; pv.y = -ETA_M * to2n;
        *(float2*)&g_pzT[((size_t)b*36 + k)*200 + oc*2] = pv;
        zmax = fmaxf(zmax, z);
    }
    __syncthreads();
    w2s[ohh*100 + oc] = zmax;
    __syncthreads();
    if (tid < 100) {
        float m = 0.f;
        #pragma unroll
        for (int k2 = 0; k2 < 6; k2++) m = fmaxf(m, w2s[k2*100 + tid]);
        w2s[600 + tid] = m;
    }
    __syncthreads();
    if (tid < 50) {
        float a = fc1b[tid];
        const float* wr = &fc1w[tid*100];
        #pragma unroll 4
        for (int k = 0; k < 100; k++) a = fmaf(w2s[600 + k], wr[k], a);
        w2s[700 + tid] = fmaxf(a, 0.f);
    }
    __syncthreads();
    if (tid < 10) {
        int idx = b*10 + tid;
        float iold = g_lii[idx], vold = g_liv[idx];
        float vnew = vold + 0.1f * (iold - vold);
        float a = 0.f;
        const float* wr = &outw[tid*50];
        #pragma unroll
        for (int j = 0; j < 50; j++) a = fmaf(w2s[700 + j], wr[j], a);
        g_liv[idx] = vnew;
        g_lii[idx] = 0.8f * iold + a;
        out[t*2560 + idx] = vnew;
    }
}

// ---------------- K4: dw1 STDP wgrad (128 blocks, 2 batches each, 3j/warp) ----------------
__global__ void __launch_bounds__(320, 2) k4_dw1(const float* __restrict__ x, int t) {
    __shared__ float pre1[2304];   // 2*1152 interleaved (tp1*ETA_P, -x*ETA_M)
    int tid = threadIdx.x;
    int wid = tid >> 5, ti = tid & 31;
    const float* xt = x + (size_t)t * XT;

    int bch = blockIdx.x;
    int i0 = ti;
    int ib0 = (i0/25)*576 + ((i0%25)/5)*24 + (i0%5);
    bool v1ok = (ti < 18);
    int i1 = ti + 32;
    int ib1 = v1ok ? (i1/25)*576 + ((i1%25)/5)*24 + (i1%5) : 0;

    float a00=0.f,a01=0.f,a10=0.f,a11=0.f,a20=0.f,a21=0.f;
    for (int bb = 0; bb < 2; bb++) {
        int b = bch*2 + bb;
        __syncthreads();
        for (int i2 = tid; i2 < XBC; i2 += 320) {
            pre1[2*i2]   = g_tp1[b*XBC + i2] * ETA_P;
            pre1[2*i2+1] = xt[b*XBC + i2] * (-ETA_M);
        }
        __syncthreads();
        const float* za = &g_z2[b*12000 + wid*400];
        const float* zbp = &g_z2[b*12000 + (wid+10)*400];
        const float* zc = &g_z2[b*12000 + (wid+20)*400];
        const float* ta = &g_to1[b*12000 + wid*400];
        const float* tb = &g_to1[b*12000 + (wid+10)*400];
        const float* tc = &g_to1[b*12000 + (wid+20)*400];

        for (int oh = 0; oh < 20; oh++) {
            int kb = oh*20, ob = oh*24;
            #pragma unroll
            for (int og = 0; og < 5; og++) {
                float4 z4a = *(const float4*)&za[kb + og*4];
                float4 z4b = *(const float4*)&zbp[kb + og*4];
                float4 z4c = *(const float4*)&zc[kb + og*4];
                float4 t4a = *(const float4*)&ta[kb + og*4];
                float4 t4b = *(const float4*)&tb[kb + og*4];
                float4 t4c = *(const float4*)&tc[kb + og*4];
                const float* zfa = &z4a.x; const float* zfb = &z4b.x; const float* zfc = &z4c.x;
                const float* tfa = &t4a.x; const float* tfb = &t4b.x; const float* tfc = &t4c.x;
                #pragma unroll
                for (int oi = 0; oi < 4; oi++) {
                    int kofs = ob + og*4 + oi;
                    float2 pc0 = *(const float2*)&pre1[2*(ib0 + kofs)];
                    a00 = fmaf(zfa[oi], pc0.x, a00); a00 = fmaf(tfa[oi], pc0.y, a00);
                    a10 = fmaf(zfb[oi], pc0.x, a10); a10 = fmaf(tfb[oi], pc0.y, a10);
                    a20 = fmaf(zfc[oi], pc0.x, a20); a20 = fmaf(tfc[oi], pc0.y, a20);
                    if (v1ok) {
                        float2 pc1 = *(const float2*)&pre1[2*(ib1 + kofs)];
                        a01 = fmaf(zfa[oi], pc1.x, a01); a01 = fmaf(tfa[oi], pc1.y, a01);
                        a11 = fmaf(zfb[oi], pc1.x, a11); a11 = fmaf(tfb[oi], pc1.y, a11);
                        a21 = fmaf(zfc[oi], pc1.x, a21); a21 = fmaf(tfc[oi], pc1.y, a21);
                    }
                }
            }
        }
    }
    int base = bch*1500;
    g_dw1p[base + wid*50 + i0]      = a00;
    g_dw1p[base + (wid+10)*50 + i0] = a10;
    g_dw1p[base + (wid+20)*50 + i0] = a20;
    if (v1ok) {
        g_dw1p[base + wid*50 + i1]      = a01;
        g_dw1p[base + (wid+10)*50 + i1] = a11;
        g_dw1p[base + (wid+20)*50 + i1] = a21;
    }
}

// ---------------- K5: dw2 STDP wgrad (320 blocks; 10j x 5i per warp; lean regs, 3 blocks/SM) ----------------
__global__ void __launch_bounds__(320, 3) k5_dw2(void) {
    __shared__ float pre2s[8192];  // 4096 interleaved float2 (tp2*ETA_P, z3)
    __shared__ float zt[1440];     // [36 k][20 j] float2 (z5, -ETA_M*to2)
    int tid = threadIdx.x;
    int wid = tid >> 5, ti = tid & 31;
    int r = blockIdx.x;
    int jt = r % 5, bch = r / 5;
    int iw = wid >> 1, jw = wid & 1;

    int ibase[5];
    #pragma unroll
    for (int m = 0; m < 5; m++) {
        int i = iw*150 + m*32 + ti;
        ibase[m] = (i/25)*PPL + ((i%25)/5)*13 + (i%5);
    }
    float acc[10][5];
    #pragma unroll
    for (int p = 0; p < 10; p++)
        #pragma unroll
        for (int m = 0; m < 5; m++) acc[p][m] = 0.f;

    for (int bb = 0; bb < 4; bb++) {
        int b = bch*4 + bb;
        __syncthreads();
        {
            const float4* src = (const float4*)&g_pre2p[(size_t)b*PRE2SL*2];
            float4* dst = (float4*)pre2s;
            for (int i2 = tid; i2 < 2048; i2 += 320) dst[i2] = src[i2];
        }
        {
            const float4* zsrc = (const float4*)&g_pzT[(size_t)b*7200];
            float4* zdst = (float4*)zt;
            for (int i2 = tid; i2 < 360; i2 += 320) {
                int k = i2 / 10, q = i2 % 10;
                zdst[k*10 + q] = zsrc[k*50 + jt*10 + q];
            }
        }
        __syncthreads();
        for (int oh = 0; oh < 6; oh++) {
            #pragma unroll
            for (int ow = 0; ow < 6; ow++) {
                int k = oh*6 + ow, kofs = oh*13 + ow;
                float pt[5], pz[5];
                #pragma unroll
                for (int m = 0; m < 5; m++) {
                    float2 p = *(const float2*)&pre2s[2*(ibase[m] + kofs)];
                    pt[m] = p.x; pz[m] = p.y;
                }
                const float4* zl = (const float4*)&zt[k*40 + jw*20];
                #pragma unroll
                for (int q = 0; q < 5; q++) {
                    float4 v = zl[q];
                    #pragma unroll
                    for (int m = 0; m < 5; m++) {
                        acc[2*q][m]   = fmaf(v.x, pt[m], acc[2*q][m]);
                        acc[2*q][m]   = fmaf(v.y, pz[m], acc[2*q][m]);
                        acc[2*q+1][m] = fmaf(v.z, pt[m], acc[2*q+1][m]);
                        acc[2*q+1][m] = fmaf(v.w, pz[m], acc[2*q+1][m]);
                    }
                }
            }
        }
    }
    size_t pbase = (size_t)bch*75000;
    #pragma unroll
    for (int p = 0; p < 10; p++) {
        int j = jt*20 + jw*10 + p;
        float* dst = &g_dw2p[pbase + j*750];
        #pragma unroll
        for (int m = 0; m < 5; m++) {
            int il = m*32 + ti;
            if (il < 150) dst[iw*150 + il] = acc[p][m];
        }
    }
}

// ---------------- K6: reduce dw + weight update ----------------
__global__ void k6_finish(void) {
    int bi = blockIdx.x, tid = threadIdx.x;
    if (bi < 293) {
        int c = bi*256 + tid;
        if (c < 75000) {
            float s = 0.f;
            #pragma unroll 8
            for (int ch = 0; ch < DW2CH; ch++) s += g_dw2p[(size_t)ch*75000 + c];
            float w = g_w2[c] + s;
            g_w2[c] = fminf(fmaxf(w, 0.f), 1.f);
        }
    } else {
        int c = (bi - 293)*256 + tid;
        if (c < 1500) {
            float s = 0.f;
            #pragma unroll 8
            for (int ch = 0; ch < DW1CH; ch++) s += g_dw1p[ch*1500 + c];
            float w = g_w1[c] + s;
            g_w1[c] = fminf(fmaxf(w, 0.f), 1.f);
        }
    }
}

// ---------------- launcher ----------------
extern "C" void kernel_launch(void* const* d_in, const int* in_sizes, int n_in,
                              void* d_out, int out_size) {
    const float* x     = (const float*)d_in[0];
    const float* w1    = (const float*)d_in[1];
    const float* w2    = (const float*)d_in[2];
    const float* fc1_w = (const float*)d_in[3];
    const float* fc1_b = (const float*)d_in[4];
    const float* out_w = (const float*)d_in[5];
    float* out = (float*)d_out;

    k_init<<<(L1SZ + 255) / 256, 256>>>(w1, w2);
    for (int t = 0; t < T; t++) {
        k1_conv1<<<B + 36, 256>>>(x, t);
        k3_conv2<<<B, 600>>>(fc1_w, fc1_b, out_w, out, t);
        k5_dw2<<<5*DW2CH, 320>>>();
        k4_dw1<<<DW1CH, 320>>>(x, t);
        k6_finish<<<299, 256>>>();
    }
}

// round 10
// speedup vs baseline: 1.4211x; 1.4211x over previous
#include <cuda_runtime.h>
#include <cuda_bf16.h>
#include <cstdint>

// ---------------- constants ----------------
#define B       256
#define T       32
#define XBC     1152        // 2*24*24
#define XT      (B*XBC)
#define A1      400         // 20*20
#define L1SZ    (B*30*A1)   // 3,072,000
#define L3SZ    (B*30*100)  // 768,000
#define L2SZ    (B*100*36)  // 921,600
#define DW1CH   128         // 2 batches per chunk
#define DW2CH   32          // 8 batches per chunk

#define VTH1    15.0f
#define VTH2    10.0f
#define DEC     0.02f
#define ETA_P   0.004f
#define ETA_M   0.003f

// padded pre2 layout: plane stride 133 (30 planes -> 3990, pad to 4096 slots/batch)
#define PPL     133
#define PRE2SL  4096

// ---------------- persistent device state ----------------
__device__ float g_w1[1500];
__device__ float g_w2[75000];
__device__ float g_v1[L1SZ];
__device__ float g_v2[L2SZ];
__device__ float g_tp1[XT];
__device__ float g_to1[L1SZ];
__device__ float g_pre2p[B*PRE2SL*2];     // interleaved (tp2*ETA_P, z3), padded layout
__device__ float g_to2[L2SZ];
__device__ float g_z2[L1SZ];
__device__ float g_z3[L3SZ];
__device__ float g_pzT[B*36*200];         // [b][k][j] float2 = (z5, -ETA_M*to2)
__device__ float g_liv[B*10];
__device__ float g_lii[B*10];
__device__ float g_dw1p[DW1CH*1500];
__device__ float g_dw2p[(size_t)DW2CH*75000];

// ---------------- init ----------------
__global__ void k_init(const float* __restrict__ w1, const float* __restrict__ w2) {
    int i = blockIdx.x * blockDim.x + threadIdx.x;
    if (i < L1SZ) { g_v1[i] = 0.f; g_to1[i] = 0.f; }
    if (i < L2SZ) { g_v2[i] = 0.f; g_to2[i] = 0.f; }
    if (i < XT)   g_tp1[i] = 0.f;
    if (i < B*PRE2SL*2) g_pre2p[i] = 0.f;
    if (i < B*10) { g_liv[i] = 0.f; g_lii[i] = 0.f; }
    if (i < 1500)  g_w1[i] = w1[i];
    if (i < 75000) g_w2[i] = w2[i];
}

// ---------------- K1: conv1 + IAF + to1 trace + fused pool/tp2(padded,scaled); extra blocks: tp1 ----------------
__global__ void k1_conv1(const float* __restrict__ x, int t) {
    const float* xt = x + (size_t)t * XT;
    int tid = threadIdx.x;
    if (blockIdx.x >= B) {
        int base = (blockIdx.x - B) * 8192;
        #pragma unroll 4
        for (int r = 0; r < 32; r++) {
            int i = base + r * 256 + tid;
            float tt = g_tp1[i];
            g_tp1[i] = tt - DEC * tt + xt[i];
        }
        return;
    }
    int b = blockIdx.x;
    __shared__ float xs[XBC];
    __shared__ float w1T[50 * 32];
    for (int i = tid; i < XBC; i += 256) xs[i] = xt[b * XBC + i];
    for (int i = tid; i < 1600; i += 256) {
        int c = i >> 5, oc = i & 31;
        w1T[i] = (oc < 30) ? g_w1[oc * 50 + c] : 0.f;
    }
    __syncthreads();

    for (int p = tid; p < A1; p += 256) {
        int oh = p / 20, ow = p % 20;
        float patch[50];
        #pragma unroll
        for (int ic = 0; ic < 2; ic++)
            #pragma unroll
            for (int kh = 0; kh < 5; kh++)
                #pragma unroll
                for (int kw = 0; kw < 5; kw++)
                    patch[ic*25 + kh*5 + kw] = xs[ic*576 + (oh+kh)*24 + ow + kw];

        for (int g = 0; g < 8; g++) {
            float a0=0.f, a1=0.f, a2=0.f, a3=0.f;
            #pragma unroll
            for (int c = 0; c < 50; c++) {
                float4 w = *(const float4*)&w1T[c*32 + g*4];
                a0 = fmaf(patch[c], w.x, a0);
                a1 = fmaf(patch[c], w.y, a1);
                a2 = fmaf(patch[c], w.z, a2);
                a3 = fmaf(patch[c], w.w, a3);
            }
            float av[4] = {a0, a1, a2, a3};
            #pragma unroll
            for (int q = 0; q < 4; q++) {
                int oc = g*4 + q;
                if (oc < 30) {
                    int idx = b*12000 + oc*A1 + p;
                    float v = g_v1[idx] + av[q];
                    float z = (v > VTH1) ? 1.f : 0.f;
                    g_v1[idx] = v * (1.f - z);
                    g_z2[idx] = z;
                    float tt = g_to1[idx];
                    g_to1[idx] = tt - DEC * tt + z;
                }
            }
        }
    }
    // fused maxpool 2x2 + z3 + scaled/padded tp2 trace
    __syncthreads();
    for (int e = tid; e < 3000; e += 256) {
        int c = e / 100, q = e % 100;
        int oh = q / 10, ow = q % 10;
        int base = b*12000 + c*A1 + oh*40 + ow*2;
        float m = fmaxf(fmaxf(g_z2[base], g_z2[base+1]),
                        fmaxf(g_z2[base+20], g_z2[base+21]));
        g_z3[b*3000 + e] = m;
        int slot = c*PPL + oh*13 + ow;
        float2* pp = (float2*)&g_pre2p[((size_t)b*PRE2SL + slot)*2];
        float2 o = *pp;
        float s = o.x;
        s = s - DEC*s + ETA_P*m;
        float2 nv; nv.x = s; nv.y = m;
        *pp = nv;
    }
}

// ---------------- K3: conv2 (x10) + IAF + to2 trace + pzT + z6 + FC/LI readout ----------------
__global__ void k3_conv2(const float* __restrict__ fc1w, const float* __restrict__ fc1b,
                         const float* __restrict__ outw, float* __restrict__ out, int t) {
    __shared__ float z3s[3000];
    __shared__ float w2s[7500];
    int b = blockIdx.x, tid = threadIdx.x;
    for (int i = tid; i < 3000; i += 600) z3s[i] = g_z3[b*3000 + i];

    int oc = tid % 100, ohh = tid / 100;
    float acc[6] = {0.f,0.f,0.f,0.f,0.f,0.f};

    for (int ic0 = 0; ic0 < 30; ic0 += 3) {
        __syncthreads();
        for (int i = tid; i < 7500; i += 600) {
            int o2 = i / 75, cc = i % 75;
            w2s[i] = g_w2[o2*750 + ic0*25 + cc];
        }
        __syncthreads();
        #pragma unroll
        for (int icl = 0; icl < 3; icl++) {
            const float* zb = &z3s[(ic0 + icl)*100];
            const float* wb = &w2s[oc*75 + icl*25];
            #pragma unroll
            for (int kh = 0; kh < 5; kh++) {
                float r[10];
                const float* zrow = &zb[(ohh + kh)*10];
                #pragma unroll
                for (int u = 0; u < 5; u++) {
                    float2 v = *(const float2*)&zrow[2*u];
                    r[2*u] = v.x; r[2*u+1] = v.y;
                }
                #pragma unroll
                for (int kw = 0; kw < 5; kw++) {
                    float w = wb[kh*5 + kw];
                    #pragma unroll
                    for (int ow = 0; ow < 6; ow++)
                        acc[ow] = fmaf(w, r[ow + kw], acc[ow]);
                }
            }
        }
    }
    // IAF epilogue
    float zmax = 0.f;
    int obase = b*3600 + oc*36 + ohh*6;
    #pragma unroll
    for (int ow = 0; ow < 6; ow++) {
        int idx = obase + ow;
        float v = g_v2[idx] + 10.0f * acc[ow];
        float z = (v > VTH2) ? 1.f : 0.f;
        g_v2[idx] = v * (1.f - z);
        float tt = g_to2[idx];
        float to2n = tt - DEC * tt + z;
        g_to2[idx] = to2n;
        int k = ohh*6 + ow;
        float2 pv; pv.x = z; pv.y = -ETA_M * to2n;
        *(float2*)&g_pzT[((size_t)b*36 + k)*200 + oc*2] = pv;
        zmax = fmaxf(zmax, z);
    }
    __syncthreads();
    w2s[ohh*100 + oc] = zmax;
    __syncthreads();
    if (tid < 100) {
        float m = 0.f;
        #pragma unroll
        for (int k2 = 0; k2 < 6; k2++) m = fmaxf(m, w2s[k2*100 + tid]);
        w2s[600 + tid] = m;
    }
    __syncthreads();
    if (tid < 50) {
        float a = fc1b[tid];
        const float* wr = &fc1w[tid*100];
        #pragma unroll 4
        for (int k = 0; k < 100; k++) a = fmaf(w2s[600 + k], wr[k], a);
        w2s[700 + tid] = fmaxf(a, 0.f);
    }
    __syncthreads();
    if (tid < 10) {
        int idx = b*10 + tid;
        float iold = g_lii[idx], vold = g_liv[idx];
        float vnew = vold + 0.1f * (iold - vold);
        float a = 0.f;
        const float* wr = &outw[tid*50];
        #pragma unroll
        for (int j = 0; j < 50; j++) a = fmaf(w2s[700 + j], wr[j], a);
        g_liv[idx] = vnew;
        g_lii[idx] = 0.8f * iold + a;
        out[t*2560 + idx] = vnew;
    }
}

// ---------------- K45: fused STDP wgrad partials (dw1 3j/warp; dw2 10j x 5i/warp, 8 batches) ----------------
__global__ void __launch_bounds__(320, 2) k45_stdp(const float* __restrict__ x, int t) {
    __shared__ float smem[9632];   // dw2: pre2s[8192] | zt[1440]; dw1: pre1[2304]
    int bi = blockIdx.x, tid = threadIdx.x;
    int wid = tid >> 5, ti = tid & 31;
    const float* xt = x + (size_t)t * XT;

    if (bi < DW1CH) {
        // ---- dw1: block = 2 batches; warp wid handles j = wid, wid+10, wid+20 ----
        float* pre1 = smem;   // 2*1152 interleaved (tp1*ETA_P, -x*ETA_M)
        int bch = bi;
        int i0 = ti;
        int ib0 = (i0/25)*576 + ((i0%25)/5)*24 + (i0%5);
        bool v1ok = (ti < 18);
        int i1 = ti + 32;
        int ib1 = v1ok ? (i1/25)*576 + ((i1%25)/5)*24 + (i1%5) : 0;

        float a00=0.f,a01=0.f,a10=0.f,a11=0.f,a20=0.f,a21=0.f;
        for (int bb = 0; bb < 2; bb++) {
            int b = bch*2 + bb;
            __syncthreads();
            for (int i2 = tid; i2 < XBC; i2 += 320) {
                pre1[2*i2]   = g_tp1[b*XBC + i2] * ETA_P;
                pre1[2*i2+1] = xt[b*XBC + i2] * (-ETA_M);
            }
            __syncthreads();
            const float* za = &g_z2[b*12000 + wid*400];
            const float* zbp = &g_z2[b*12000 + (wid+10)*400];
            const float* zc = &g_z2[b*12000 + (wid+20)*400];
            const float* ta = &g_to1[b*12000 + wid*400];
            const float* tb = &g_to1[b*12000 + (wid+10)*400];
            const float* tc = &g_to1[b*12000 + (wid+20)*400];

            for (int oh = 0; oh < 20; oh++) {
                int kb = oh*20, ob = oh*24;
                #pragma unroll
                for (int og = 0; og < 5; og++) {
                    float4 z4a = *(const float4*)&za[kb + og*4];
                    float4 z4b = *(const float4*)&zbp[kb + og*4];
                    float4 z4c = *(const float4*)&zc[kb + og*4];
                    float4 t4a = *(const float4*)&ta[kb + og*4];
                    float4 t4b = *(const float4*)&tb[kb + og*4];
                    float4 t4c = *(const float4*)&tc[kb + og*4];
                    const float* zfa = &z4a.x; const float* zfb = &z4b.x; const float* zfc = &z4c.x;
                    const float* tfa = &t4a.x; const float* tfb = &t4b.x; const float* tfc = &t4c.x;
                    #pragma unroll
                    for (int oi = 0; oi < 4; oi++) {
                        int kofs = ob + og*4 + oi;
                        float2 pc0 = *(const float2*)&pre1[2*(ib0 + kofs)];
                        a00 = fmaf(zfa[oi], pc0.x, a00); a00 = fmaf(tfa[oi], pc0.y, a00);
                        a10 = fmaf(zfb[oi], pc0.x, a10); a10 = fmaf(tfb[oi], pc0.y, a10);
                        a20 = fmaf(zfc[oi], pc0.x, a20); a20 = fmaf(tfc[oi], pc0.y, a20);
                        if (v1ok) {
                            float2 pc1 = *(const float2*)&pre1[2*(ib1 + kofs)];
                            a01 = fmaf(zfa[oi], pc1.x, a01); a01 = fmaf(tfa[oi], pc1.y, a01);
                            a11 = fmaf(zfb[oi], pc1.x, a11); a11 = fmaf(tfb[oi], pc1.y, a11);
                            a21 = fmaf(zfc[oi], pc1.x, a21); a21 = fmaf(tfc[oi], pc1.y, a21);
                        }
                    }
                }
            }
        }
        int base = bch*1500;
        g_dw1p[base + wid*50 + i0]      = a00;
        g_dw1p[base + (wid+10)*50 + i0] = a10;
        g_dw1p[base + (wid+20)*50 + i0] = a20;
        if (v1ok) {
            g_dw1p[base + wid*50 + i1]      = a01;
            g_dw1p[base + (wid+10)*50 + i1] = a11;
            g_dw1p[base + (wid+20)*50 + i1] = a21;
        }
    } else {
        // ---- dw2: 5 jtiles(20 j) x 32 bchunks(8 b) ----
        // warp = (iw = wid>>1, jw = wid&1); 10 j = jt*20+jw*10+p, 5 i-slots i = iw*150 + m*32 + ti
        int r = bi - DW1CH;
        int jt = r % 5, bch = r / 5;
        float* pre2s = smem;         // [8192] = 4096 interleaved float2 (tp2*ETA_P, z3)
        float* zt    = smem + 8192;  // [1440] = [36 k][20 j] float2 (z5, -ETA_M*to2)
        int iw = wid >> 1, jw = wid & 1;

        int ibase[5];
        bool vm[5];
        #pragma unroll
        for (int m = 0; m < 5; m++) {
            int il = m*32 + ti;
            vm[m] = (il < 150);
            int i = iw*150 + il;
            ibase[m] = (i/25)*PPL + ((i%25)/5)*13 + (i%5);
        }
        float acc[10][5];
        #pragma unroll
        for (int p = 0; p < 10; p++)
            #pragma unroll
            for (int m = 0; m < 5; m++) acc[p][m] = 0.f;

        for (int bb = 0; bb < 8; bb++) {
            int b = bch*8 + bb;
            __syncthreads();
            {
                const float4* src = (const float4*)&g_pre2p[(size_t)b*PRE2SL*2];
                float4* dst = (float4*)pre2s;
                for (int i2 = tid; i2 < 2048; i2 += 320) dst[i2] = src[i2];
            }
            {
                const float4* zsrc = (const float4*)&g_pzT[(size_t)b*7200];
                float4* zdst = (float4*)zt;
                for (int i2 = tid; i2 < 360; i2 += 320) {
                    int k = i2 / 10, q = i2 % 10;
                    zdst[k*10 + q] = zsrc[k*50 + jt*10 + q];
                }
            }
            __syncthreads();
            for (int oh = 0; oh < 6; oh++) {
                #pragma unroll
                for (int ow = 0; ow < 6; ow++) {
                    int k = oh*6 + ow, kofs = oh*13 + ow;
                    float pt[5], pz[5];
                    #pragma unroll
                    for (int m = 0; m < 5; m++) {
                        float2 p = *(const float2*)&pre2s[2*(ibase[m] + kofs)];
                        pt[m] = p.x; pz[m] = p.y;
                    }
                    const float4* zl = (const float4*)&zt[k*40 + jw*20];
                    #pragma unroll
                    for (int q = 0; q < 5; q++) {
                        float4 v = zl[q];   // j-pairs 2q (x,y) and 2q+1 (z,w)
                        #pragma unroll
                        for (int m = 0; m < 5; m++) {
                            acc[2*q][m]   = fmaf(v.x, pt[m], acc[2*q][m]);
                            acc[2*q][m]   = fmaf(v.y, pz[m], acc[2*q][m]);
                            acc[2*q+1][m] = fmaf(v.z, pt[m], acc[2*q+1][m]);
                            acc[2*q+1][m] = fmaf(v.w, pz[m], acc[2*q+1][m]);
                        }
                    }
                }
            }
        }
        size_t pbase = (size_t)bch*75000;
        #pragma unroll
        for (int p = 0; p < 10; p++) {
            int j = jt*20 + jw*10 + p;
            float* dst = &g_dw2p[pbase + j*750];
            #pragma unroll
            for (int m = 0; m < 5; m++) {
                if (vm[m]) dst[iw*150 + m*32 + ti] = acc[p][m];
            }
        }
    }
}

// ---------------- K6: reduce dw + weight update ----------------
__global__ void k6_finish(void) {
    int bi = blockIdx.x, tid = threadIdx.x;
    if (bi < 293) {
        int c = bi*256 + tid;
        if (c < 75000) {
            float s = 0.f;
            #pragma unroll 8
            for (int ch = 0; ch < DW2CH; ch++) s += g_dw2p[(size_t)ch*75000 + c];
            float w = g_w2[c] + s;
            g_w2[c] = fminf(fmaxf(w, 0.f), 1.f);
        }
    } else {
        int c = (bi - 293)*256 + tid;
        if (c < 1500) {
            float s = 0.f;
            #pragma unroll 8
            for (int ch = 0; ch < DW1CH; ch++) s += g_dw1p[ch*1500 + c];
            float w = g_w1[c] + s;
            g_w1[c] = fminf(fmaxf(w, 0.f), 1.f);
        }
    }
}

// ---------------- launcher ----------------
extern "C" void kernel_launch(void* const* d_in, const int* in_sizes, int n_in,
                              void* d_out, int out_size) {
    const float* x     = (const float*)d_in[0];
    const float* w1    = (const float*)d_in[1];
    const float* w2    = (const float*)d_in[2];
    const float* fc1_w = (const float*)d_in[3];
    const float* fc1_b = (const float*)d_in[4];
    const float* out_w = (const float*)d_in[5];
    float* out = (float*)d_out;

    k_init<<<(L1SZ + 255) / 256, 256>>>(w1, w2);
    for (int t = 0; t < T; t++) {
        k1_conv1<<<B + 36, 256>>>(x, t);
        k3_conv2<<<B, 600>>>(fc1_w, fc1_b, out_w, out, t);
        k45_stdp<<<DW1CH + 5*DW2CH, 320>>>(x, t);
        k6_finish<<<299, 256>>>();
    }
}

// round 11
// speedup vs baseline: 1.5333x; 1.0790x over previous
#include <cuda_runtime.h>
#include <cuda_bf16.h>
#include <cstdint>

// ---------------- constants ----------------
#define B       256
#define T       32
#define XBC     1152        // 2*24*24
#define XT      (B*XBC)
#define A1      400         // 20*20
#define L1SZ    (B*30*A1)   // 3,072,000
#define L3SZ    (B*30*100)  // 768,000
#define L2SZ    (B*100*36)  // 921,600
#define DW1CH   128         // 2 batches per chunk
#define DW2CH   32          // 8 batches per chunk

#define VTH1    15.0f
#define VTH2    10.0f
#define DEC     0.02f
#define ETA_P   0.004f
#define ETA_M   0.003f

// padded pre2 layout: plane stride 133 (30 planes -> 3990, pad to 4096 slots/batch)
#define PPL     133
#define PRE2SL  4096

// ---------------- packed fp32x2 helpers (sm_100 FFMA2) ----------------
__device__ __forceinline__ void ffma2(uint64_t& d, uint64_t a, uint64_t b) {
    asm("fma.rn.f32x2 %0, %1, %2, %0;" : "+l"(d) : "l"(a), "l"(b));
}
__device__ __forceinline__ uint64_t pack2(float lo, float hi) {
    uint64_t r; asm("mov.b64 %0, {%1, %2};" : "=l"(r) : "f"(lo), "f"(hi)); return r;
}
__device__ __forceinline__ void unpack2(uint64_t v, float& lo, float& hi) {
    asm("mov.b64 {%0, %1}, %2;" : "=f"(lo), "=f"(hi) : "l"(v));
}

// ---------------- persistent device state ----------------
__device__ float g_w1[1500];
__device__ float g_w2[75000];
__device__ float g_v1[L1SZ];
__device__ float g_v2[L2SZ];
__device__ float g_tp1[XT];
__device__ float g_to1[L1SZ];
__device__ float g_pre2p[B*PRE2SL*2];     // interleaved (tp2*ETA_P, z3), padded layout
__device__ float g_to2[L2SZ];
__device__ float g_z2[L1SZ];
__device__ float g_z3[L3SZ];
__device__ float g_pzA[B*3600];           // [b][k][j] z5
__device__ float g_pzB[B*3600];           // [b][k][j] -ETA_M*to2
__device__ float g_liv[B*10];
__device__ float g_lii[B*10];
__device__ float g_dw1p[DW1CH*1500];
__device__ float g_dw2p[(size_t)DW2CH*75000];

// ---------------- init ----------------
__global__ void k_init(const float* __restrict__ w1, const float* __restrict__ w2) {
    int i = blockIdx.x * blockDim.x + threadIdx.x;
    if (i < L1SZ) { g_v1[i] = 0.f; g_to1[i] = 0.f; }
    if (i < L2SZ) { g_v2[i] = 0.f; g_to2[i] = 0.f; }
    if (i < XT)   g_tp1[i] = 0.f;
    if (i < B*PRE2SL*2) g_pre2p[i] = 0.f;
    if (i < B*10) { g_liv[i] = 0.f; g_lii[i] = 0.f; }
    if (i < 1500)  g_w1[i] = w1[i];
    if (i < 75000) g_w2[i] = w2[i];
}

// ---------------- K1: conv1 + IAF + to1 trace + fused pool/tp2(padded,scaled); extra blocks: tp1 ----------------
__global__ void k1_conv1(const float* __restrict__ x, int t) {
    const float* xt = x + (size_t)t * XT;
    int tid = threadIdx.x;
    if (blockIdx.x >= B) {
        int base = (blockIdx.x - B) * 8192;
        #pragma unroll 4
        for (int r = 0; r < 32; r++) {
            int i = base + r * 256 + tid;
            float tt = g_tp1[i];
            g_tp1[i] = tt - DEC * tt + xt[i];
        }
        return;
    }
    int b = blockIdx.x;
    __shared__ float xs[XBC];
    __shared__ float w1T[50 * 32];
    for (int i = tid; i < XBC; i += 256) xs[i] = xt[b * XBC + i];
    for (int i = tid; i < 1600; i += 256) {
        int c = i >> 5, oc = i & 31;
        w1T[i] = (oc < 30) ? g_w1[oc * 50 + c] : 0.f;
    }
    __syncthreads();

    for (int p = tid; p < A1; p += 256) {
        int oh = p / 20, ow = p % 20;
        float patch[50];
        #pragma unroll
        for (int ic = 0; ic < 2; ic++)
            #pragma unroll
            for (int kh = 0; kh < 5; kh++)
                #pragma unroll
                for (int kw = 0; kw < 5; kw++)
                    patch[ic*25 + kh*5 + kw] = xs[ic*576 + (oh+kh)*24 + ow + kw];

        for (int g = 0; g < 8; g++) {
            float a0=0.f, a1=0.f, a2=0.f, a3=0.f;
            #pragma unroll
            for (int c = 0; c < 50; c++) {
                float4 w = *(const float4*)&w1T[c*32 + g*4];
                a0 = fmaf(patch[c], w.x, a0);
                a1 = fmaf(patch[c], w.y, a1);
                a2 = fmaf(patch[c], w.z, a2);
                a3 = fmaf(patch[c], w.w, a3);
            }
            float av[4] = {a0, a1, a2, a3};
            #pragma unroll
            for (int q = 0; q < 4; q++) {
                int oc = g*4 + q;
                if (oc < 30) {
                    int idx = b*12000 + oc*A1 + p;
                    float v = g_v1[idx] + av[q];
                    float z = (v > VTH1) ? 1.f : 0.f;
                    g_v1[idx] = v * (1.f - z);
                    g_z2[idx] = z;
                    float tt = g_to1[idx];
                    g_to1[idx] = tt - DEC * tt + z;
                }
            }
        }
    }
    // fused maxpool 2x2 + z3 + scaled/padded tp2 trace
    __syncthreads();
    for (int e = tid; e < 3000; e += 256) {
        int c = e / 100, q = e % 100;
        int oh = q / 10, ow = q % 10;
        int base = b*12000 + c*A1 + oh*40 + ow*2;
        float m = fmaxf(fmaxf(g_z2[base], g_z2[base+1]),
                        fmaxf(g_z2[base+20], g_z2[base+21]));
        g_z3[b*3000 + e] = m;
        int slot = c*PPL + oh*13 + ow;
        float2* pp = (float2*)&g_pre2p[((size_t)b*PRE2SL + slot)*2];
        float2 o = *pp;
        float s = o.x;
        s = s - DEC*s + ETA_P*m;
        float2 nv; nv.x = s; nv.y = m;
        *pp = nv;
    }
}

// ---------------- K3: conv2 (x10) + IAF + to2 trace + pzA/pzB + z6 + FC/LI readout ----------------
__global__ void k3_conv2(const float* __restrict__ fc1w, const float* __restrict__ fc1b,
                         const float* __restrict__ outw, float* __restrict__ out, int t) {
    __shared__ float z3s[3000];
    __shared__ float w2s[7500];
    int b = blockIdx.x, tid = threadIdx.x;
    for (int i = tid; i < 3000; i += 600) z3s[i] = g_z3[b*3000 + i];

    int oc = tid % 100, ohh = tid / 100;
    float acc[6] = {0.f,0.f,0.f,0.f,0.f,0.f};

    for (int ic0 = 0; ic0 < 30; ic0 += 3) {
        __syncthreads();
        for (int i = tid; i < 7500; i += 600) {
            int o2 = i / 75, cc = i % 75;
            w2s[i] = g_w2[o2*750 + ic0*25 + cc];
        }
        __syncthreads();
        #pragma unroll
        for (int icl = 0; icl < 3; icl++) {
            const float* zb = &z3s[(ic0 + icl)*100];
            const float* wb = &w2s[oc*75 + icl*25];
            #pragma unroll
            for (int kh = 0; kh < 5; kh++) {
                float r[10];
                const float* zrow = &zb[(ohh + kh)*10];
                #pragma unroll
                for (int u = 0; u < 5; u++) {
                    float2 v = *(const float2*)&zrow[2*u];
                    r[2*u] = v.x; r[2*u+1] = v.y;
                }
                #pragma unroll
                for (int kw = 0; kw < 5; kw++) {
                    float w = wb[kh*5 + kw];
                    #pragma unroll
                    for (int ow = 0; ow < 6; ow++)
                        acc[ow] = fmaf(w, r[ow + kw], acc[ow]);
                }
            }
        }
    }
    // IAF epilogue
    float zmax = 0.f;
    int obase = b*3600 + oc*36 + ohh*6;
    #pragma unroll
    for (int ow = 0; ow < 6; ow++) {
        int idx = obase + ow;
        float v = g_v2[idx] + 10.0f * acc[ow];
        float z = (v > VTH2) ? 1.f : 0.f;
        g_v2[idx] = v * (1.f - z);
        float tt = g_to2[idx];
        float to2n = tt - DEC * tt + z;
        g_to2[idx] = to2n;
        int k = ohh*6 + ow;
        g_pzA[(size_t)b*3600 + k*100 + oc] = z;
        g_pzB[(size_t)b*3600 + k*100 + oc] = -ETA_M * to2n;
        zmax = fmaxf(zmax, z);
    }
    __syncthreads();
    w2s[ohh*100 + oc] = zmax;
    __syncthreads();
    if (tid < 100) {
        float m = 0.f;
        #pragma unroll
        for (int k2 = 0; k2 < 6; k2++) m = fmaxf(m, w2s[k2*100 + tid]);
        w2s[600 + tid] = m;
    }
    __syncthreads();
    if (tid < 50) {
        float a = fc1b[tid];
        const float* wr = &fc1w[tid*100];
        #pragma unroll 4
        for (int k = 0; k < 100; k++) a = fmaf(w2s[600 + k], wr[k], a);
        w2s[700 + tid] = fmaxf(a, 0.f);
    }
    __syncthreads();
    if (tid < 10) {
        int idx = b*10 + tid;
        float iold = g_lii[idx], vold = g_liv[idx];
        float vnew = vold + 0.1f * (iold - vold);
        float a = 0.f;
        const float* wr = &outw[tid*50];
        #pragma unroll
        for (int j = 0; j < 50; j++) a = fmaf(w2s[700 + j], wr[j], a);
        g_liv[idx] = vnew;
        g_lii[idx] = 0.8f * iold + a;
        out[t*2560 + idx] = vnew;
    }
}

// ---------------- K45: fused STDP wgrad (dw1 3j/warp; dw2 FFMA2-packed 10j x 5i/warp, 8 batches) ----------------
__global__ void __launch_bounds__(320, 2) k45_stdp(const float* __restrict__ x, int t) {
    __shared__ float smem[9632];   // dw2: pre2s[8192] | zA[720] | zB[720]; dw1: pre1[2304]
    int bi = blockIdx.x, tid = threadIdx.x;
    int wid = tid >> 5, ti = tid & 31;
    const float* xt = x + (size_t)t * XT;

    if (bi < DW1CH) {
        // ---- dw1: block = 2 batches; warp wid handles j = wid, wid+10, wid+20 ----
        float* pre1 = smem;   // 2*1152 interleaved (tp1*ETA_P, -x*ETA_M)
        int bch = bi;
        int i0 = ti;
        int ib0 = (i0/25)*576 + ((i0%25)/5)*24 + (i0%5);
        bool v1ok = (ti < 18);
        int i1 = ti + 32;
        int ib1 = v1ok ? (i1/25)*576 + ((i1%25)/5)*24 + (i1%5) : 0;

        float a00=0.f,a01=0.f,a10=0.f,a11=0.f,a20=0.f,a21=0.f;
        for (int bb = 0; bb < 2; bb++) {
            int b = bch*2 + bb;
            __syncthreads();
            for (int i2 = tid; i2 < XBC; i2 += 320) {
                pre1[2*i2]   = g_tp1[b*XBC + i2] * ETA_P;
                pre1[2*i2+1] = xt[b*XBC + i2] * (-ETA_M);
            }
            __syncthreads();
            const float* za = &g_z2[b*12000 + wid*400];
            const float* zbp = &g_z2[b*12000 + (wid+10)*400];
            const float* zc = &g_z2[b*12000 + (wid+20)*400];
            const float* ta = &g_to1[b*12000 + wid*400];
            const float* tb = &g_to1[b*12000 + (wid+10)*400];
            const float* tc = &g_to1[b*12000 + (wid+20)*400];

            for (int oh = 0; oh < 20; oh++) {
                int kb = oh*20, ob = oh*24;
                #pragma unroll
                for (int og = 0; og < 5; og++) {
                    float4 z4a = *(const float4*)&za[kb + og*4];
                    float4 z4b = *(const float4*)&zbp[kb + og*4];
                    float4 z4c = *(const float4*)&zc[kb + og*4];
                    float4 t4a = *(const float4*)&ta[kb + og*4];
                    float4 t4b = *(const float4*)&tb[kb + og*4];
                    float4 t4c = *(const float4*)&tc[kb + og*4];
                    const float* zfa = &z4a.x; const float* zfb = &z4b.x; const float* zfc = &z4c.x;
                    const float* tfa = &t4a.x; const float* tfb = &t4b.x; const float* tfc = &t4c.x;
                    #pragma unroll
                    for (int oi = 0; oi < 4; oi++) {
                        int kofs = ob + og*4 + oi;
                        float2 pc0 = *(const float2*)&pre1[2*(ib0 + kofs)];
                        a00 = fmaf(zfa[oi], pc0.x, a00); a00 = fmaf(tfa[oi], pc0.y, a00);
                        a10 = fmaf(zfb[oi], pc0.x, a10); a10 = fmaf(tfb[oi], pc0.y, a10);
                        a20 = fmaf(zfc[oi], pc0.x, a20); a20 = fmaf(tfc[oi], pc0.y, a20);
                        if (v1ok) {
                            float2 pc1 = *(const float2*)&pre1[2*(ib1 + kofs)];
                            a01 = fmaf(zfa[oi], pc1.x, a01); a01 = fmaf(tfa[oi], pc1.y, a01);
                            a11 = fmaf(zfb[oi], pc1.x, a11); a11 = fmaf(tfb[oi], pc1.y, a11);
                            a21 = fmaf(zfc[oi], pc1.x, a21); a21 = fmaf(tfc[oi], pc1.y, a21);
                        }
                    }
                }
            }
        }
        int base = bch*1500;
        g_dw1p[base + wid*50 + i0]      = a00;
        g_dw1p[base + (wid+10)*50 + i0] = a10;
        g_dw1p[base + (wid+20)*50 + i0] = a20;
        if (v1ok) {
            g_dw1p[base + wid*50 + i1]      = a01;
            g_dw1p[base + (wid+10)*50 + i1] = a11;
            g_dw1p[base + (wid+20)*50 + i1] = a21;
        }
    } else {
        // ---- dw2: 5 jtiles(20 j) x 32 bchunks(8 b); FFMA2 packed j-pairs ----
        // warp = (iw = wid>>1, jw = wid&1); 10 j = jt*20+jw*10+p (5 packed pairs), 5 i-slots
        int r = bi - DW1CH;
        int jt = r % 5, bch = r / 5;
        float* pre2s = smem;          // [8192] = 4096 interleaved float2 (tp2*ETA_P, z3)
        float* zA    = smem + 8192;   // [720] = [36 k][20 j] z5
        float* zB    = smem + 8912;   // [720] = [36 k][20 j] -ETA_M*to2
        int iw = wid >> 1, jw = wid & 1;

        int ibase[5];
        bool vm[5];
        #pragma unroll
        for (int m = 0; m < 5; m++) {
            int il = m*32 + ti;
            vm[m] = (il < 150);
            int i = iw*150 + il;
            ibase[m] = (i/25)*PPL + ((i%25)/5)*13 + (i%5);
        }
        uint64_t accp[5][5];   // [jpair q][m], lanes = (j=..+2q, j=..+2q+1)
        #pragma unroll
        for (int q = 0; q < 5; q++)
            #pragma unroll
            for (int m = 0; m < 5; m++) accp[q][m] = 0ull;

        for (int bb = 0; bb < 8; bb++) {
            int b = bch*8 + bb;
            __syncthreads();
            {
                const float4* src = (const float4*)&g_pre2p[(size_t)b*PRE2SL*2];
                float4* dst = (float4*)pre2s;
                for (int i2 = tid; i2 < 2048; i2 += 320) dst[i2] = src[i2];
            }
            {
                const float2* sA = (const float2*)&g_pzA[(size_t)b*3600];
                const float2* sB = (const float2*)&g_pzB[(size_t)b*3600];
                float2* dA = (float2*)zA;
                float2* dB = (float2*)zB;
                for (int i2 = tid; i2 < 360; i2 += 320) {
                    int k = i2 / 10, q = i2 % 10;
                    dA[k*10 + q] = sA[k*50 + jt*10 + q];
                    dB[k*10 + q] = sB[k*50 + jt*10 + q];
                }
            }
            __syncthreads();
            for (int oh = 0; oh < 6; oh++) {
                #pragma unroll
                for (int ow = 0; ow < 6; ow++) {
                    int k = oh*6 + ow, kofs = oh*13 + ow;
                    const uint64_t* zar = (const uint64_t*)&zA[k*20 + jw*10];
                    const uint64_t* zbr = (const uint64_t*)&zB[k*20 + jw*10];
                    uint64_t jz[5], jo[5];
                    #pragma unroll
                    for (int q = 0; q < 5; q++) { jz[q] = zar[q]; jo[q] = zbr[q]; }
                    #pragma unroll
                    for (int m = 0; m < 5; m++) {
                        float2 p = *(const float2*)&pre2s[2*(ibase[m] + kofs)];
                        uint64_t ptd = pack2(p.x, p.x);
                        uint64_t pzd = pack2(p.y, p.y);
                        #pragma unroll
                        for (int q = 0; q < 5; q++) {
                            ffma2(accp[q][m], jz[q], ptd);
                            ffma2(accp[q][m], jo[q], pzd);
                        }
                    }
                }
            }
        }
        size_t pbase = (size_t)bch*75000;
        #pragma unroll
        for (int q = 0; q < 5; q++) {
            int j0 = jt*20 + jw*10 + 2*q;
            float* d0 = &g_dw2p[pbase + j0*750];
            float* d1 = &g_dw2p[pbase + (j0+1)*750];
            #pragma unroll
            for (int m = 0; m < 5; m++) {
                float lo, hi;
                unpack2(accp[q][m], lo, hi);
                if (vm[m]) {
                    int i = iw*150 + m*32 + ti;
                    d0[i] = lo;
                    d1[i] = hi;
                }
            }
        }
    }
}

// ---------------- K6: reduce dw + weight update ----------------
__global__ void k6_finish(void) {
    int bi = blockIdx.x, tid = threadIdx.x;
    if (bi < 293) {
        int c = bi*256 + tid;
        if (c < 75000) {
            float s = 0.f;
            #pragma unroll 8
            for (int ch = 0; ch < DW2CH; ch++) s += g_dw2p[(size_t)ch*75000 + c];
            float w = g_w2[c] + s;
            g_w2[c] = fminf(fmaxf(w, 0.f), 1.f);
        }
    } else {
        int c = (bi - 293)*256 + tid;
        if (c < 1500) {
            float s = 0.f;
            #pragma unroll 8
            for (int ch = 0; ch < DW1CH; ch++) s += g_dw1p[ch*1500 + c];
            float w = g_w1[c] + s;
            g_w1[c] = fminf(fmaxf(w, 0.f), 1.f);
        }
    }
}

// ---------------- launcher ----------------
extern "C" void kernel_launch(void* const* d_in, const int* in_sizes, int n_in,
                              void* d_out, int out_size) {
    const float* x     = (const float*)d_in[0];
    const float* w1    = (const float*)d_in[1];
    const float* w2    = (const float*)d_in[2];
    const float* fc1_w = (const float*)d_in[3];
    const float* fc1_b = (const float*)d_in[4];
    const float* out_w = (const float*)d_in[5];
    float* out = (float*)d_out;

    k_init<<<(L1SZ + 255) / 256, 256>>>(w1, w2);
    for (int t = 0; t < T; t++) {
        k1_conv1<<<B + 36, 256>>>(x, t);
        k3_conv2<<<B, 600>>>(fc1_w, fc1_b, out_w, out, t);
        k45_stdp<<<DW1CH + 5*DW2CH, 320>>>(x, t);
        k6_finish<<<299, 256>>>();
    }
}

// round 12
// speedup vs baseline: 1.5840x; 1.0330x over previous
#include <cuda_runtime.h>
#include <cuda_bf16.h>
#include <cstdint>

// ---------------- constants ----------------
#define B       256
#define T       32
#define XBC     1152        // 2*24*24
#define XT      (B*XBC)
#define A1      400         // 20*20
#define L1SZ    (B*30*A1)   // 3,072,000
#define L3SZ    (B*30*100)  // 768,000
#define L2SZ    (B*100*36)  // 921,600
#define DW1CH   128         // 2 batches per chunk
#define DW2CH   32          // 8 batches per chunk

#define VTH1    15.0f
#define VTH2    10.0f
#define DEC     0.02f
#define ETA_P   0.004f
#define ETA_M   0.003f

// padded pre2 layout: plane stride 133 (30 planes -> 3990, pad to 4096 slots/batch)
#define PPL     133
#define PRE2SL  4096

// ---------------- packed fp32x2 helpers (sm_100 FFMA2) ----------------
__device__ __forceinline__ void ffma2(uint64_t& d, uint64_t a, uint64_t b) {
    asm("fma.rn.f32x2 %0, %1, %2, %0;" : "+l"(d) : "l"(a), "l"(b));
}
__device__ __forceinline__ uint64_t pack2(float lo, float hi) {
    uint64_t r; asm("mov.b64 %0, {%1, %2};" : "=l"(r) : "f"(lo), "f"(hi)); return r;
}
__device__ __forceinline__ void unpack2(uint64_t v, float& lo, float& hi) {
    asm("mov.b64 {%0, %1}, %2;" : "=f"(lo), "=f"(hi) : "l"(v));
}

// ---------------- persistent device state ----------------
__device__ float g_w1[1500];
__device__ float g_w2[75000];
__device__ float g_v1[L1SZ];
__device__ float g_v2[L2SZ];
__device__ float g_tp1[XT];
__device__ float g_to1[L1SZ];
__device__ float g_pre2pA[B*PRE2SL];      // planar tp2*ETA_P, padded layout
__device__ float g_pre2pB[B*PRE2SL];      // planar z3, padded layout
__device__ float g_to2[L2SZ];
__device__ float g_z2[L1SZ];
__device__ float g_z3[L3SZ];
__device__ float g_pzA[B*3600];           // [b][k][j] z5
__device__ float g_pzB[B*3600];           // [b][k][j] -ETA_M*to2
__device__ float g_liv[B*10];
__device__ float g_lii[B*10];
__device__ float g_dw1p[DW1CH*1500];
__device__ float g_dw2p[(size_t)DW2CH*75000];

// ---------------- init ----------------
__global__ void k_init(const float* __restrict__ w1, const float* __restrict__ w2) {
    int i = blockIdx.x * blockDim.x + threadIdx.x;
    if (i < L1SZ) { g_v1[i] = 0.f; g_to1[i] = 0.f; }
    if (i < L2SZ) { g_v2[i] = 0.f; g_to2[i] = 0.f; }
    if (i < XT)   g_tp1[i] = 0.f;
    if (i < B*PRE2SL) { g_pre2pA[i] = 0.f; g_pre2pB[i] = 0.f; }
    if (i < B*10) { g_liv[i] = 0.f; g_lii[i] = 0.f; }
    if (i < 1500)  g_w1[i] = w1[i];
    if (i < 75000) g_w2[i] = w2[i];
}

// ---------------- K1: conv1 + IAF + to1 trace + fused pool/tp2(planar,scaled); extra blocks: tp1 ----------------
__global__ void k1_conv1(const float* __restrict__ x, int t) {
    const float* xt = x + (size_t)t * XT;
    int tid = threadIdx.x;
    if (blockIdx.x >= B) {
        int base = (blockIdx.x - B) * 8192;
        #pragma unroll 4
        for (int r = 0; r < 32; r++) {
            int i = base + r * 256 + tid;
            float tt = g_tp1[i];
            g_tp1[i] = tt - DEC * tt + xt[i];
        }
        return;
    }
    int b = blockIdx.x;
    __shared__ float xs[XBC];
    __shared__ float w1T[50 * 32];
    for (int i = tid; i < XBC; i += 256) xs[i] = xt[b * XBC + i];
    for (int i = tid; i < 1600; i += 256) {
        int c = i >> 5, oc = i & 31;
        w1T[i] = (oc < 30) ? g_w1[oc * 50 + c] : 0.f;
    }
    __syncthreads();

    for (int p = tid; p < A1; p += 256) {
        int oh = p / 20, ow = p % 20;
        float patch[50];
        #pragma unroll
        for (int ic = 0; ic < 2; ic++)
            #pragma unroll
            for (int kh = 0; kh < 5; kh++)
                #pragma unroll
                for (int kw = 0; kw < 5; kw++)
                    patch[ic*25 + kh*5 + kw] = xs[ic*576 + (oh+kh)*24 + ow + kw];

        for (int g = 0; g < 8; g++) {
            float a0=0.f, a1=0.f, a2=0.f, a3=0.f;
            #pragma unroll
            for (int c = 0; c < 50; c++) {
                float4 w = *(const float4*)&w1T[c*32 + g*4];
                a0 = fmaf(patch[c], w.x, a0);
                a1 = fmaf(patch[c], w.y, a1);
                a2 = fmaf(patch[c], w.z, a2);
                a3 = fmaf(patch[c], w.w, a3);
            }
            float av[4] = {a0, a1, a2, a3};
            #pragma unroll
            for (int q = 0; q < 4; q++) {
                int oc = g*4 + q;
                if (oc < 30) {
                    int idx = b*12000 + oc*A1 + p;
                    float v = g_v1[idx] + av[q];
                    float z = (v > VTH1) ? 1.f : 0.f;
                    g_v1[idx] = v * (1.f - z);
                    g_z2[idx] = z;
                    float tt = g_to1[idx];
                    g_to1[idx] = tt - DEC * tt + z;
                }
            }
        }
    }
    // fused maxpool 2x2 + z3 + scaled planar tp2 trace
    __syncthreads();
    for (int e = tid; e < 3000; e += 256) {
        int c = e / 100, q = e % 100;
        int oh = q / 10, ow = q % 10;
        int base = b*12000 + c*A1 + oh*40 + ow*2;
        float m = fmaxf(fmaxf(g_z2[base], g_z2[base+1]),
                        fmaxf(g_z2[base+20], g_z2[base+21]));
        g_z3[b*3000 + e] = m;
        int slot = (size_t)b*PRE2SL + c*PPL + oh*13 + ow;
        float s = g_pre2pA[slot];
        s = s - DEC*s + ETA_P*m;
        g_pre2pA[slot] = s;
        g_pre2pB[slot] = m;
    }
}

// ---------------- K3: conv2 (x10) + IAF + to2 trace + pzA/pzB + z6 + FC/LI readout ----------------
__global__ void k3_conv2(const float* __restrict__ fc1w, const float* __restrict__ fc1b,
                         const float* __restrict__ outw, float* __restrict__ out, int t) {
    __shared__ float z3s[3000];
    __shared__ float w2s[7500];
    int b = blockIdx.x, tid = threadIdx.x;
    for (int i = tid; i < 3000; i += 600) z3s[i] = g_z3[b*3000 + i];

    int oc = tid % 100, ohh = tid / 100;
    float acc[6] = {0.f,0.f,0.f,0.f,0.f,0.f};

    for (int ic0 = 0; ic0 < 30; ic0 += 3) {
        __syncthreads();
        for (int i = tid; i < 7500; i += 600) {
            int o2 = i / 75, cc = i % 75;
            w2s[i] = g_w2[o2*750 + ic0*25 + cc];
        }
        __syncthreads();
        #pragma unroll
        for (int icl = 0; icl < 3; icl++) {
            const float* zb = &z3s[(ic0 + icl)*100];
            const float* wb = &w2s[oc*75 + icl*25];
            #pragma unroll
            for (int kh = 0; kh < 5; kh++) {
                float r[10];
                const float* zrow = &zb[(ohh + kh)*10];
                #pragma unroll
                for (int u = 0; u < 5; u++) {
                    float2 v = *(const float2*)&zrow[2*u];
                    r[2*u] = v.x; r[2*u+1] = v.y;
                }
                #pragma unroll
                for (int kw = 0; kw < 5; kw++) {
                    float w = wb[kh*5 + kw];
                    #pragma unroll
                    for (int ow = 0; ow < 6; ow++)
                        acc[ow] = fmaf(w, r[ow + kw], acc[ow]);
                }
            }
        }
    }
    // IAF epilogue
    float zmax = 0.f;
    int obase = b*3600 + oc*36 + ohh*6;
    #pragma unroll
    for (int ow = 0; ow < 6; ow++) {
        int idx = obase + ow;
        float v = g_v2[idx] + 10.0f * acc[ow];
        float z = (v > VTH2) ? 1.f : 0.f;
        g_v2[idx] = v * (1.f - z);
        float tt = g_to2[idx];
        float to2n = tt - DEC * tt + z;
        g_to2[idx] = to2n;
        int k = ohh*6 + ow;
        g_pzA[(size_t)b*3600 + k*100 + oc] = z;
        g_pzB[(size_t)b*3600 + k*100 + oc] = -ETA_M * to2n;
        zmax = fmaxf(zmax, z);
    }
    __syncthreads();
    w2s[ohh*100 + oc] = zmax;
    __syncthreads();
    if (tid < 100) {
        float m = 0.f;
        #pragma unroll
        for (int k2 = 0; k2 < 6; k2++) m = fmaxf(m, w2s[k2*100 + tid]);
        w2s[600 + tid] = m;
    }
    __syncthreads();
    if (tid < 50) {
        float a = fc1b[tid];
        const float* wr = &fc1w[tid*100];
        #pragma unroll 4
        for (int k = 0; k < 100; k++) a = fmaf(w2s[600 + k], wr[k], a);
        w2s[700 + tid] = fmaxf(a, 0.f);
    }
    __syncthreads();
    if (tid < 10) {
        int idx = b*10 + tid;
        float iold = g_lii[idx], vold = g_liv[idx];
        float vnew = vold + 0.1f * (iold - vold);
        float a = 0.f;
        const float* wr = &outw[tid*50];
        #pragma unroll
        for (int j = 0; j < 50; j++) a = fmaf(w2s[700 + j], wr[j], a);
        g_liv[idx] = vnew;
        g_lii[idx] = 0.8f * iold + a;
        out[t*2560 + idx] = vnew;
    }
}

// ---------------- K45: fused STDP wgrad (dw1 3j/warp; dw2 FFMA2, planar pre + packed zAB) ----------------
__global__ void __launch_bounds__(320, 2) k45_stdp(const float* __restrict__ x, int t) {
    __shared__ float smem[9632];   // dw2: pts[4096] | pzs[4096] | zAB[1440]; dw1: pre1[2304]
    int bi = blockIdx.x, tid = threadIdx.x;
    int wid = tid >> 5, ti = tid & 31;
    const float* xt = x + (size_t)t * XT;

    if (bi < DW1CH) {
        // ---- dw1: block = 2 batches; warp wid handles j = wid, wid+10, wid+20 ----
        float* pre1 = smem;   // 2*1152 interleaved (tp1*ETA_P, -x*ETA_M)
        int bch = bi;
        int i0 = ti;
        int ib0 = (i0/25)*576 + ((i0%25)/5)*24 + (i0%5);
        bool v1ok = (ti < 18);
        int i1 = ti + 32;
        int ib1 = v1ok ? (i1/25)*576 + ((i1%25)/5)*24 + (i1%5) : 0;

        float a00=0.f,a01=0.f,a10=0.f,a11=0.f,a20=0.f,a21=0.f;
        for (int bb = 0; bb < 2; bb++) {
            int b = bch*2 + bb;
            __syncthreads();
            for (int i2 = tid; i2 < XBC; i2 += 320) {
                pre1[2*i2]   = g_tp1[b*XBC + i2] * ETA_P;
                pre1[2*i2+1] = xt[b*XBC + i2] * (-ETA_M);
            }
            __syncthreads();
            const float* za = &g_z2[b*12000 + wid*400];
            const float* zbp = &g_z2[b*12000 + (wid+10)*400];
            const float* zc = &g_z2[b*12000 + (wid+20)*400];
            const float* ta = &g_to1[b*12000 + wid*400];
            const float* tb = &g_to1[b*12000 + (wid+10)*400];
            const float* tc = &g_to1[b*12000 + (wid+20)*400];

            for (int oh = 0; oh < 20; oh++) {
                int kb = oh*20, ob = oh*24;
                #pragma unroll
                for (int og = 0; og < 5; og++) {
                    float4 z4a = *(const float4*)&za[kb + og*4];
                    float4 z4b = *(const float4*)&zbp[kb + og*4];
                    float4 z4c = *(const float4*)&zc[kb + og*4];
                    float4 t4a = *(const float4*)&ta[kb + og*4];
                    float4 t4b = *(const float4*)&tb[kb + og*4];
                    float4 t4c = *(const float4*)&tc[kb + og*4];
                    const float* zfa = &z4a.x; const float* zfb = &z4b.x; const float* zfc = &z4c.x;
                    const float* tfa = &t4a.x; const float* tfb = &t4b.x; const float* tfc = &t4c.x;
                    #pragma unroll
                    for (int oi = 0; oi < 4; oi++) {
                        int kofs = ob + og*4 + oi;
                        float2 pc0 = *(const float2*)&pre1[2*(ib0 + kofs)];
                        a00 = fmaf(zfa[oi], pc0.x, a00); a00 = fmaf(tfa[oi], pc0.y, a00);
                        a10 = fmaf(zfb[oi], pc0.x, a10); a10 = fmaf(tfb[oi], pc0.y, a10);
                        a20 = fmaf(zfc[oi], pc0.x, a20); a20 = fmaf(tfc[oi], pc0.y, a20);
                        if (v1ok) {
                            float2 pc1 = *(const float2*)&pre1[2*(ib1 + kofs)];
                            a01 = fmaf(zfa[oi], pc1.x, a01); a01 = fmaf(tfa[oi], pc1.y, a01);
                            a11 = fmaf(zfb[oi], pc1.x, a11); a11 = fmaf(tfb[oi], pc1.y, a11);
                            a21 = fmaf(zfc[oi], pc1.x, a21); a21 = fmaf(tfc[oi], pc1.y, a21);
                        }
                    }
                }
            }
        }
        int base = bch*1500;
        g_dw1p[base + wid*50 + i0]      = a00;
        g_dw1p[base + (wid+10)*50 + i0] = a10;
        g_dw1p[base + (wid+20)*50 + i0] = a20;
        if (v1ok) {
            g_dw1p[base + wid*50 + i1]      = a01;
            g_dw1p[base + (wid+10)*50 + i1] = a11;
            g_dw1p[base + (wid+20)*50 + i1] = a21;
        }
    } else {
        // ---- dw2: 5 jtiles(20 j) x 32 bchunks(8 b); FFMA2 packed j-pairs, planar pre ----
        int r = bi - DW1CH;
        int jt = r % 5, bch = r / 5;
        float* pts = smem;            // [4096] planar tp2*ETA_P
        float* pzs = smem + 4096;     // [4096] planar z3
        float* zAB = smem + 8192;     // [1440] = [36 k][10 jpair] float4 (z5_2q, z5_2q+1, o_2q, o_2q+1)
        int iw = wid >> 1, jw = wid & 1;

        int ibase[5];
        bool vm[5];
        #pragma unroll
        for (int m = 0; m < 5; m++) {
            int il = m*32 + ti;
            vm[m] = (il < 150);
            int i = iw*150 + il;
            ibase[m] = (i/25)*PPL + ((i%25)/5)*13 + (i%5);
        }
        uint64_t accp[5][5];   // [jpair q][m]
        #pragma unroll
        for (int q = 0; q < 5; q++)
            #pragma unroll
            for (int m = 0; m < 5; m++) accp[q][m] = 0ull;

        for (int bb = 0; bb < 8; bb++) {
            int b = bch*8 + bb;
            __syncthreads();
            {
                const float4* srcA = (const float4*)&g_pre2pA[(size_t)b*PRE2SL];
                const float4* srcB = (const float4*)&g_pre2pB[(size_t)b*PRE2SL];
                float4* dA = (float4*)pts;
                float4* dB = (float4*)pzs;
                for (int i2 = tid; i2 < 1024; i2 += 320) {
                    dA[i2] = srcA[i2];
                    dB[i2] = srcB[i2];
                }
            }
            {
                const float2* sA = (const float2*)&g_pzA[(size_t)b*3600];
                const float2* sB = (const float2*)&g_pzB[(size_t)b*3600];
                float4* dz = (float4*)zAB;
                for (int i2 = tid; i2 < 360; i2 += 320) {
                    int k = i2 / 10, q = i2 % 10;
                    float2 a = sA[k*50 + jt*10 + q];
                    float2 o = sB[k*50 + jt*10 + q];
                    float4 v; v.x = a.x; v.y = a.y; v.z = o.x; v.w = o.y;
                    dz[k*10 + q] = v;
                }
            }
            __syncthreads();
            for (int oh = 0; oh < 6; oh++) {
                #pragma unroll
                for (int ow = 0; ow < 6; ow++) {
                    int k = oh*6 + ow, kofs = oh*13 + ow;
                    const float4* zl = (const float4*)&zAB[(k*10 + jw*5)*4];
                    uint64_t jz[5], jo[5];
                    #pragma unroll
                    for (int q = 0; q < 5; q++) {
                        float4 v = zl[q];
                        jz[q] = pack2(v.x, v.y);
                        jo[q] = pack2(v.z, v.w);
                    }
                    #pragma unroll
                    for (int m = 0; m < 5; m++) {
                        float pt = pts[ibase[m] + kofs];
                        float pz = pzs[ibase[m] + kofs];
                        uint64_t ptd = pack2(pt, pt);
                        uint64_t pzd = pack2(pz, pz);
                        #pragma unroll
                        for (int q = 0; q < 5; q++) {
                            ffma2(accp[q][m], jz[q], ptd);
                            ffma2(accp[q][m], jo[q], pzd);
                        }
                    }
                }
            }
        }
        size_t pbase = (size_t)bch*75000;
        #pragma unroll
        for (int q = 0; q < 5; q++) {
            int j0 = jt*20 + jw*10 + 2*q;
            float* d0 = &g_dw2p[pbase + j0*750];
            float* d1 = &g_dw2p[pbase + (j0+1)*750];
            #pragma unroll
            for (int m = 0; m < 5; m++) {
                float lo, hi;
                unpack2(accp[q][m], lo, hi);
                if (vm[m]) {
                    int i = iw*150 + m*32 + ti;
                    d0[i] = lo;
                    d1[i] = hi;
                }
            }
        }
    }
}

// ---------------- K6: reduce dw + weight update ----------------
__global__ void k6_finish(void) {
    int bi = blockIdx.x, tid = threadIdx.x;
    if (bi < 293) {
        int c = bi*256 + tid;
        if (c < 75000) {
            float s = 0.f;
            #pragma unroll 8
            for (int ch = 0; ch < DW2CH; ch++) s += g_dw2p[(size_t)ch*75000 + c];
            float w = g_w2[c] + s;
            g_w2[c] = fminf(fmaxf(w, 0.f), 1.f);
        }
    } else {
        int c = (bi - 293)*256 + tid;
        if (c < 1500) {
            float s = 0.f;
            #pragma unroll 8
            for (int ch = 0; ch < DW1CH; ch++) s += g_dw1p[ch*1500 + c];
            float w = g_w1[c] + s;
            g_w1[c] = fminf(fmaxf(w, 0.f), 1.f);
        }
    }
}

// ---------------- launcher ----------------
extern "C" void kernel_launch(void* const* d_in, const int* in_sizes, int n_in,
                              void* d_out, int out_size) {
    const float* x     = (const float*)d_in[0];
    const float* w1    = (const float*)d_in[1];
    const float* w2    = (const float*)d_in[2];
    const float* fc1_w = (const float*)d_in[3];
    const float* fc1_b = (const float*)d_in[4];
    const float* out_w = (const float*)d_in[5];
    float* out = (float*)d_out;

    k_init<<<(L1SZ + 255) / 256, 256>>>(w1, w2);
    for (int t = 0; t < T; t++) {
        k1_conv1<<<B + 36, 256>>>(x, t);
        k3_conv2<<<B, 600>>>(fc1_w, fc1_b, out_w, out, t);
        k45_stdp<<<DW1CH + 5*DW2CH, 320>>>(x, t);
        k6_finish<<<299, 256>>>();
    }
}

// round 14
// speedup vs baseline: 1.5924x; 1.0053x over previous
#include <cuda_runtime.h>
#include <cuda_bf16.h>
#include <cstdint>

// ---------------- constants ----------------
#define B       256
#define T       32
#define XBC     1152        // 2*24*24
#define XT      (B*XBC)
#define A1      400         // 20*20
#define L1SZ    (B*30*A1)   // 3,072,000
#define L3SZ    (B*30*100)  // 768,000
#define L2SZ    (B*100*36)  // 921,600
#define DW1CH   128         // 2 batches per chunk
#define DW2CH   32          // 8 batches per chunk

#define VTH1    15.0f
#define VTH2    10.0f
#define DEC     0.02f
#define ETA_P   0.004f
#define ETA_M   0.003f

// padded pre2 layout: plane stride 133 (30 planes -> 3990, pad to 4096 slots/batch)
#define PPL     133
#define PRE2SL  4096

// ---------------- packed fp32x2 helpers (sm_100 FFMA2) ----------------
__device__ __forceinline__ void ffma2(uint64_t& d, uint64_t a, uint64_t b) {
    asm("fma.rn.f32x2 %0, %1, %2, %0;" : "+l"(d) : "l"(a), "l"(b));
}
__device__ __forceinline__ uint64_t pack2(float lo, float hi) {
    uint64_t r; asm("mov.b64 %0, {%1, %2};" : "=l"(r) : "f"(lo), "f"(hi)); return r;
}
__device__ __forceinline__ void unpack2(uint64_t v, float& lo, float& hi) {
    asm("mov.b64 {%0, %1}, %2;" : "=f"(lo), "=f"(hi) : "l"(v));
}

// ---------------- persistent device state ----------------
__device__ float g_w1[1500];
__device__ float g_w2[75000];
__device__ float g_v1[L1SZ];
__device__ float g_v2[L2SZ];
__device__ float g_tp1[XT];
__device__ float g_to1[L1SZ];
__device__ float g_pre2pA[B*PRE2SL];      // planar tp2*ETA_P, padded layout
__device__ float g_pre2pB[B*PRE2SL];      // planar z3, padded layout
__device__ float g_to2[L2SZ];
__device__ float g_z2[L1SZ];
__device__ float g_z3[L3SZ];
__device__ float g_pzA[B*3600];           // [b][k][j] z5
__device__ float g_pzB[B*3600];           // [b][k][j] -ETA_M*to2
__device__ float g_liv[B*10];
__device__ float g_lii[B*10];
__device__ float g_dw1p[DW1CH*1500];
__device__ float g_dw2p[(size_t)DW2CH*75000];

// ---------------- init ----------------
__global__ void k_init(const float* __restrict__ w1, const float* __restrict__ w2) {
    int i = blockIdx.x * blockDim.x + threadIdx.x;
    if (i < L1SZ) { g_v1[i] = 0.f; g_to1[i] = 0.f; }
    if (i < L2SZ) { g_v2[i] = 0.f; g_to2[i] = 0.f; }
    if (i < XT)   g_tp1[i] = 0.f;
    if (i < B*PRE2SL) { g_pre2pA[i] = 0.f; g_pre2pB[i] = 0.f; }
    if (i < B*10) { g_liv[i] = 0.f; g_lii[i] = 0.f; }
    if (i < 1500)  g_w1[i] = w1[i];
    if (i < 75000) g_w2[i] = w2[i];
}

// ---------------- K1: conv1 + IAF + to1 trace + fused pool/tp2(planar,scaled); extra blocks: tp1 ----------------
// 384 threads: p-loop covers 400 pixels in ~1 iteration (was 2 with 256 threads)
__global__ void k1_conv1(const float* __restrict__ x, int t) {
    const float* xt = x + (size_t)t * XT;
    int tid = threadIdx.x;
    if (blockIdx.x >= B) {
        int base = (blockIdx.x - B) * 8192;
        for (int i = tid; i < 8192; i += 384) {
            float tt = g_tp1[base + i];
            g_tp1[base + i] = tt - DEC * tt + xt[base + i];
        }
        return;
    }
    int b = blockIdx.x;
    __shared__ float xs[XBC];
    __shared__ float w1T[50 * 32];
    for (int i = tid; i < XBC; i += 384) xs[i] = xt[b * XBC + i];
    for (int i = tid; i < 1600; i += 384) {
        int c = i >> 5, oc = i & 31;
        w1T[i] = (oc < 30) ? g_w1[oc * 50 + c] : 0.f;
    }
    __syncthreads();

    for (int p = tid; p < A1; p += 384) {
        int oh = p / 20, ow = p % 20;
        float patch[50];
        #pragma unroll
        for (int ic = 0; ic < 2; ic++)
            #pragma unroll
            for (int kh = 0; kh < 5; kh++)
                #pragma unroll
                for (int kw = 0; kw < 5; kw++)
                    patch[ic*25 + kh*5 + kw] = xs[ic*576 + (oh+kh)*24 + ow + kw];

        for (int g = 0; g < 8; g++) {
            float a0=0.f, a1=0.f, a2=0.f, a3=0.f;
            #pragma unroll
            for (int c = 0; c < 50; c++) {
                float4 w = *(const float4*)&w1T[c*32 + g*4];
                a0 = fmaf(patch[c], w.x, a0);
                a1 = fmaf(patch[c], w.y, a1);
                a2 = fmaf(patch[c], w.z, a2);
                a3 = fmaf(patch[c], w.w, a3);
            }
            float av[4] = {a0, a1, a2, a3};
            #pragma unroll
            for (int q = 0; q < 4; q++) {
                int oc = g*4 + q;
                if (oc < 30) {
                    int idx = b*12000 + oc*A1 + p;
                    float v = g_v1[idx] + av[q];
                    float z = (v > VTH1) ? 1.f : 0.f;
                    g_v1[idx] = v * (1.f - z);
                    g_z2[idx] = z;
                    float tt = g_to1[idx];
                    g_to1[idx] = tt - DEC * tt + z;
                }
            }
        }
    }
    // fused maxpool 2x2 + z3 + scaled planar tp2 trace
    __syncthreads();
    for (int e = tid; e < 3000; e += 384) {
        int c = e / 100, q = e % 100;
        int oh = q / 10, ow = q % 10;
        int base = b*12000 + c*A1 + oh*40 + ow*2;
        float m = fmaxf(fmaxf(g_z2[base], g_z2[base+1]),
                        fmaxf(g_z2[base+20], g_z2[base+21]));
        g_z3[b*3000 + e] = m;
        int slot = (size_t)b*PRE2SL + c*PPL + oh*13 + ow;
        float s = g_pre2pA[slot];
        s = s - DEC*s + ETA_P*m;
        g_pre2pA[slot] = s;
        g_pre2pB[slot] = m;
    }
}

// ---------------- K3: conv2 (x10, FFMA2) + IAF + to2 trace + pzA/pzB + z6 + FC/LI readout ----------------
__global__ void k3_conv2(const float* __restrict__ fc1w, const float* __restrict__ fc1b,
                         const float* __restrict__ outw, float* __restrict__ out, int t) {
    __shared__ float z3s[3000];
    __shared__ float w2s[7500];
    int b = blockIdx.x, tid = threadIdx.x;
    for (int i = tid; i < 3000; i += 600) z3s[i] = g_z3[b*3000 + i];

    int oc = tid % 100, ohh = tid / 100;
    uint64_t accp[3];   // (acc0,acc1),(acc2,acc3),(acc4,acc5)
    accp[0] = 0ull; accp[1] = 0ull; accp[2] = 0ull;

    for (int ic0 = 0; ic0 < 30; ic0 += 3) {
        __syncthreads();
        for (int i = tid; i < 7500; i += 600) {
            int o2 = i / 75, cc = i % 75;
            w2s[i] = g_w2[o2*750 + ic0*25 + cc];
        }
        __syncthreads();
        #pragma unroll
        for (int icl = 0; icl < 3; icl++) {
            const float* zb = &z3s[(ic0 + icl)*100];
            const float* wb = &w2s[oc*75 + icl*25];
            #pragma unroll
            for (int kh = 0; kh < 5; kh++) {
                const float* zrow = &zb[(ohh + kh)*10];
                float r[10];
                #pragma unroll
                for (int u = 0; u < 5; u++) {
                    float2 v = *(const float2*)&zrow[2*u];
                    r[2*u] = v.x; r[2*u+1] = v.y;
                }
                uint64_t rp[9];
                #pragma unroll
                for (int a = 0; a < 9; a++) rp[a] = pack2(r[a], r[a+1]);
                #pragma unroll
                for (int kw = 0; kw < 5; kw++) {
                    float w = wb[kh*5 + kw];
                    uint64_t wd = pack2(w, w);
                    ffma2(accp[0], rp[kw],     wd);
                    ffma2(accp[1], rp[kw + 2], wd);
                    ffma2(accp[2], rp[kw + 4], wd);
                }
            }
        }
    }
    float acc[6];
    unpack2(accp[0], acc[0], acc[1]);
    unpack2(accp[1], acc[2], acc[3]);
    unpack2(accp[2], acc[4], acc[5]);
    // IAF epilogue
    float zmax = 0.f;
    int obase = b*3600 + oc*36 + ohh*6;
    #pragma unroll
    for (int ow = 0; ow < 6; ow++) {
        int idx = obase + ow;
        float v = g_v2[idx] + 10.0f * acc[ow];
        float z = (v > VTH2) ? 1.f : 0.f;
        g_v2[idx] = v * (1.f - z);
        float tt = g_to2[idx];
        float to2n = tt - DEC * tt + z;
        g_to2[idx] = to2n;
        int k = ohh*6 + ow;
        g_pzA[(size_t)b*3600 + k*100 + oc] = z;
        g_pzB[(size_t)b*3600 + k*100 + oc] = -ETA_M * to2n;
        zmax = fmaxf(zmax, z);
    }
    __syncthreads();
    w2s[ohh*100 + oc] = zmax;
    __syncthreads();
    if (tid < 100) {
        float m = 0.f;
        #pragma unroll
        for (int k2 = 0; k2 < 6; k2++) m = fmaxf(m, w2s[k2*100 + tid]);
        w2s[600 + tid] = m;
    }
    __syncthreads();
    if (tid < 50) {
        float a = fc1b[tid];
        const float* wr = &fc1w[tid*100];
        #pragma unroll 4
        for (int k = 0; k < 100; k++) a = fmaf(w2s[600 + k], wr[k], a);
        w2s[700 + tid] = fmaxf(a, 0.f);
    }
    __syncthreads();
    if (tid < 10) {
        int idx = b*10 + tid;
        float iold = g_lii[idx], vold = g_liv[idx];
        float vnew = vold + 0.1f * (iold - vold);
        float a = 0.f;
        const float* wr = &outw[tid*50];
        #pragma unroll
        for (int j = 0; j < 50; j++) a = fmaf(w2s[700 + j], wr[j], a);
        g_liv[idx] = vnew;
        g_lii[idx] = 0.8f * iold + a;
        out[t*2560 + idx] = vnew;
    }
}

// ---------------- K45: fused STDP wgrad (dw1 3j/warp; dw2 FFMA2, planar pre + packed zAB) ----------------
__global__ void __launch_bounds__(320, 2) k45_stdp(const float* __restrict__ x, int t) {
    __shared__ float smem[9632];   // dw2: pts[4096] | pzs[4096] | zAB[1440]; dw1: pre1[2304]
    int bi = blockIdx.x, tid = threadIdx.x;
    int wid = tid >> 5, ti = tid & 31;
    const float* xt = x + (size_t)t * XT;

    if (bi < DW1CH) {
        // ---- dw1: block = 2 batches; warp wid handles j = wid, wid+10, wid+20 ----
        float* pre1 = smem;   // 2*1152 interleaved (tp1*ETA_P, -x*ETA_M)
        int bch = bi;
        int i0 = ti;
        int ib0 = (i0/25)*576 + ((i0%25)/5)*24 + (i0%5);
        bool v1ok = (ti < 18);
        int i1 = ti + 32;
        int ib1 = v1ok ? (i1/25)*576 + ((i1%25)/5)*24 + (i1%5) : 0;

        float a00=0.f,a01=0.f,a10=0.f,a11=0.f,a20=0.f,a21=0.f;
        for (int bb = 0; bb < 2; bb++) {
            int b = bch*2 + bb;
            __syncthreads();
            for (int i2 = tid; i2 < XBC; i2 += 320) {
                pre1[2*i2]   = g_tp1[b*XBC + i2] * ETA_P;
                pre1[2*i2+1] = xt[b*XBC + i2] * (-ETA_M);
            }
            __syncthreads();
            const float* za = &g_z2[b*12000 + wid*400];
            const float* zbp = &g_z2[b*12000 + (wid+10)*400];
            const float* zc = &g_z2[b*12000 + (wid+20)*400];
            const float* ta = &g_to1[b*12000 + wid*400];
            const float* tb = &g_to1[b*12000 + (wid+10)*400];
            const float* tc = &g_to1[b*12000 + (wid+20)*400];

            for (int oh = 0; oh < 20; oh++) {
                int kb = oh*20, ob = oh*24;
                #pragma unroll
                for (int og = 0; og < 5; og++) {
                    float4 z4a = *(const float4*)&za[kb + og*4];
                    float4 z4b = *(const float4*)&zbp[kb + og*4];
                    float4 z4c = *(const float4*)&zc[kb + og*4];
                    float4 t4a = *(const float4*)&ta[kb + og*4];
                    float4 t4b = *(const float4*)&tb[kb + og*4];
                    float4 t4c = *(const float4*)&tc[kb + og*4];
                    const float* zfa = &z4a.x; const float* zfb = &z4b.x; const float* zfc = &z4c.x;
                    const float* tfa = &t4a.x; const float* tfb = &t4b.x; const float* tfc = &t4c.x;
                    #pragma unroll
                    for (int oi = 0; oi < 4; oi++) {
                        int kofs = ob + og*4 + oi;
                        float2 pc0 = *(const float2*)&pre1[2*(ib0 + kofs)];
                        a00 = fmaf(zfa[oi], pc0.x, a00); a00 = fmaf(tfa[oi], pc0.y, a00);
                        a10 = fmaf(zfb[oi], pc0.x, a10); a10 = fmaf(tfb[oi], pc0.y, a10);
                        a20 = fmaf(zfc[oi], pc0.x, a20); a20 = fmaf(tfc[oi], pc0.y, a20);
                        if (v1ok) {
                            float2 pc1 = *(const float2*)&pre1[2*(ib1 + kofs)];
                            a01 = fmaf(zfa[oi], pc1.x, a01); a01 = fmaf(tfa[oi], pc1.y, a01);
                            a11 = fmaf(zfb[oi], pc1.x, a11); a11 = fmaf(tfb[oi], pc1.y, a11);
                            a21 = fmaf(zfc[oi], pc1.x, a21); a21 = fmaf(tfc[oi], pc1.y, a21);
                        }
                    }
                }
            }
        }
        int base = bch*1500;
        g_dw1p[base + wid*50 + i0]      = a00;
        g_dw1p[base + (wid+10)*50 + i0] = a10;
        g_dw1p[base + (wid+20)*50 + i0] = a20;
        if (v1ok) {
            g_dw1p[base + wid*50 + i1]      = a01;
            g_dw1p[base + (wid+10)*50 + i1] = a11;
            g_dw1p[base + (wid+20)*50 + i1] = a21;
        }
    } else {
        // ---- dw2: 5 jtiles(20 j) x 32 bchunks(8 b); FFMA2 packed j-pairs, planar pre ----
        int r = bi - DW1CH;
        int jt = r % 5, bch = r / 5;
        float* pts = smem;            // [4096] planar tp2*ETA_P
        float* pzs = smem + 4096;     // [4096] planar z3
        float* zAB = smem + 8192;     // [1440] = [36 k][10 jpair] float4 (z5_2q, z5_2q+1, o_2q, o_2q+1)
        int iw = wid >> 1, jw = wid & 1;

        int ibase[5];
        bool vm[5];
        #pragma unroll
        for (int m = 0; m < 5; m++) {
            int il = m*32 + ti;
            vm[m] = (il < 150);
            int i = iw*150 + il;
            ibase[m] = (i/25)*PPL + ((i%25)/5)*13 + (i%5);
        }
        uint64_t accp[5][5];   // [jpair q][m]
        #pragma unroll
        for (int q = 0; q < 5; q++)
            #pragma unroll
            for (int m = 0; m < 5; m++) accp[q][m] = 0ull;

        for (int bb = 0; bb < 8; bb++) {
            int b = bch*8 + bb;
            __syncthreads();
            {
                const float4* srcA = (const float4*)&g_pre2pA[(size_t)b*PRE2SL];
                const float4* srcB = (const float4*)&g_pre2pB[(size_t)b*PRE2SL];
                float4* dA = (float4*)pts;
                float4* dB = (float4*)pzs;
                for (int i2 = tid; i2 < 1024; i2 += 320) {
                    dA[i2] = srcA[i2];
                    dB[i2] = srcB[i2];
                }
            }
            {
                const float2* sA = (const float2*)&g_pzA[(size_t)b*3600];
                const float2* sB = (const float2*)&g_pzB[(size_t)b*3600];
                float4* dz = (float4*)zAB;
                for (int i2 = tid; i2 < 360; i2 += 320) {
                    int k = i2 / 10, q = i2 % 10;
                    float2 a = sA[k*50 + jt*10 + q];
                    float2 o = sB[k*50 + jt*10 + q];
                    float4 v; v.x = a.x; v.y = a.y; v.z = o.x; v.w = o.y;
                    dz[k*10 + q] = v;
                }
            }
            __syncthreads();
            for (int oh = 0; oh < 6; oh++) {
                #pragma unroll
                for (int ow = 0; ow < 6; ow++) {
                    int k = oh*6 + ow, kofs = oh*13 + ow;
                    const float4* zl = (const float4*)&zAB[(k*10 + jw*5)*4];
                    uint64_t jz[5], jo[5];
                    #pragma unroll
                    for (int q = 0; q < 5; q++) {
                        float4 v = zl[q];
                        jz[q] = pack2(v.x, v.y);
                        jo[q] = pack2(v.z, v.w);
                    }
                    #pragma unroll
                    for (int m = 0; m < 5; m++) {
                        float pt = pts[ibase[m] + kofs];
                        float pz = pzs[ibase[m] + kofs];
                        uint64_t ptd = pack2(pt, pt);
                        uint64_t pzd = pack2(pz, pz);
                        #pragma unroll
                        for (int q = 0; q < 5; q++) {
                            ffma2(accp[q][m], jz[q], ptd);
                            ffma2(accp[q][m], jo[q], pzd);
                        }
                    }
                }
            }
        }
        size_t pbase = (size_t)bch*75000;
        #pragma unroll
        for (int q = 0; q < 5; q++) {
            int j0 = jt*20 + jw*10 + 2*q;
            float* d0 = &g_dw2p[pbase + j0*750];
            float* d1 = &g_dw2p[pbase + (j0+1)*750];
            #pragma unroll
            for (int m = 0; m < 5; m++) {
                float lo, hi;
                unpack2(accp[q][m], lo, hi);
                if (vm[m]) {
                    int i = iw*150 + m*32 + ti;
                    d0[i] = lo;
                    d1[i] = hi;
                }
            }
        }
    }
}

// ---------------- K6: reduce dw + weight update ----------------
__global__ void k6_finish(void) {
    int bi = blockIdx.x, tid = threadIdx.x;
    if (bi < 293) {
        int c = bi*256 + tid;
        if (c < 75000) {
            float s = 0.f;
            #pragma unroll 8
            for (int ch = 0; ch < DW2CH; ch++) s += g_dw2p[(size_t)ch*75000 + c];
            float w = g_w2[c] + s;
            g_w2[c] = fminf(fmaxf(w, 0.f), 1.f);
        }
    } else {
        int c = (bi - 293)*256 + tid;
        if (c < 1500) {
            float s = 0.f;
            #pragma unroll 8
            for (int ch = 0; ch < DW1CH; ch++) s += g_dw1p[ch*1500 + c];
            float w = g_w1[c] + s;
            g_w1[c] = fminf(fmaxf(w, 0.f), 1.f);
        }
    }
}

// ---------------- launcher ----------------
extern "C" void kernel_launch(void* const* d_in, const int* in_sizes, int n_in,
                              void* d_out, int out_size) {
    const float* x     = (const float*)d_in[0];
    const float* w1    = (const float*)d_in[1];
    const float* w2    = (const float*)d_in[2];
    const float* fc1_w = (const float*)d_in[3];
    const float* fc1_b = (const float*)d_in[4];
    const float* out_w = (const float*)d_in[5];
    float* out = (float*)d_out;

    k_init<<<(L1SZ + 255) / 256, 256>>>(w1, w2);
    for (int t = 0; t < T; t++) {
        k1_conv1<<<B + 36, 384>>>(x, t);
        k3_conv2<<<B, 600>>>(fc1_w, fc1_b, out_w, out, t);
        k45_stdp<<<DW1CH + 5*DW2CH, 320>>>(x, t);
        k6_finish<<<299, 256>>>();
    }
}

// round 16
// speedup vs baseline: 1.6021x; 1.0061x over previous
#include <cuda_runtime.h>
#include <cuda_bf16.h>
#include <cstdint>

// ---------------- constants ----------------
#define B       256
#define T       32
#define XBC     1152        // 2*24*24
#define XT      (B*XBC)
#define A1      400         // 20*20
#define L1SZ    (B*30*A1)   // 3,072,000
#define L3SZ    (B*30*100)  // 768,000
#define L2SZ    (B*100*36)  // 921,600
#define DW1CH   128         // 2 batches per chunk
#define DW2CH   32          // 8 batches per chunk

#define VTH1    15.0f
#define VTH2    10.0f
#define DEC     0.02f
#define ETA_P   0.004f
#define ETA_M   0.003f

// padded pre2 layout: plane stride 133 (30 planes -> 3990, pad to 4096 slots/batch)
#define PPL     133
#define PRE2SL  4096

// ---------------- packed fp32x2 helpers (sm_100 FFMA2) ----------------
__device__ __forceinline__ void ffma2(uint64_t& d, uint64_t a, uint64_t b) {
    asm("fma.rn.f32x2 %0, %1, %2, %0;" : "+l"(d) : "l"(a), "l"(b));
}
__device__ __forceinline__ uint64_t pack2(float lo, float hi) {
    uint64_t r; asm("mov.b64 %0, {%1, %2};" : "=l"(r) : "f"(lo), "f"(hi)); return r;
}
__device__ __forceinline__ void unpack2(uint64_t v, float& lo, float& hi) {
    asm("mov.b64 {%0, %1}, %2;" : "=f"(lo), "=f"(hi) : "l"(v));
}

// ---------------- persistent device state ----------------
__device__ float g_w1[1500];
__device__ float g_w2[75000];
__device__ float g_v1[L1SZ];
__device__ float g_v2[L2SZ];
__device__ float g_tp1[XT];
__device__ float g_to1[L1SZ];
__device__ float g_pre2pA[B*PRE2SL];      // planar tp2*ETA_P, padded layout
__device__ float g_pre2pB[B*PRE2SL];      // planar z3, padded layout
__device__ float g_to2[L2SZ];
__device__ float g_z2[L1SZ];
__device__ float g_z3[L3SZ];
__device__ float g_pzA[B*3600];           // [b][k][j] z5
__device__ float g_pzB[B*3600];           // [b][k][j] -ETA_M*to2
__device__ float g_liv[B*10];
__device__ float g_lii[B*10];
__device__ float g_dw1p[DW1CH*1500];
__device__ float g_dw2p[(size_t)DW2CH*75000];

// ---------------- init ----------------
__global__ void k_init(const float* __restrict__ w1, const float* __restrict__ w2) {
    int i = blockIdx.x * blockDim.x + threadIdx.x;
    if (i < L1SZ) { g_v1[i] = 0.f; g_to1[i] = 0.f; }
    if (i < L2SZ) { g_v2[i] = 0.f; g_to2[i] = 0.f; }
    if (i < XT)   g_tp1[i] = 0.f;
    if (i < B*PRE2SL) { g_pre2pA[i] = 0.f; g_pre2pB[i] = 0.f; }
    if (i < B*10) { g_liv[i] = 0.f; g_lii[i] = 0.f; }
    if (i < 1500)  g_w1[i] = w1[i];
    if (i < 75000) g_w2[i] = w2[i];
}

// ---------------- K1: conv1 + IAF + to1 trace + fused pool/tp2(planar,scaled); extra blocks: tp1 ----------------
__global__ void k1_conv1(const float* __restrict__ x, int t) {
    const float* xt = x + (size_t)t * XT;
    int tid = threadIdx.x;
    if (blockIdx.x >= B) {
        int base = (blockIdx.x - B) * 8192;
        for (int i = tid; i < 8192; i += 384) {
            float tt = g_tp1[base + i];
            g_tp1[base + i] = tt - DEC * tt + xt[base + i];
        }
        return;
    }
    int b = blockIdx.x;
    __shared__ float xs[XBC];
    __shared__ float w1T[50 * 32];
    for (int i = tid; i < XBC; i += 384) xs[i] = xt[b * XBC + i];
    for (int i = tid; i < 1600; i += 384) {
        int c = i >> 5, oc = i & 31;
        w1T[i] = (oc < 30) ? g_w1[oc * 50 + c] : 0.f;
    }
    __syncthreads();

    for (int p = tid; p < A1; p += 384) {
        int oh = p / 20, ow = p % 20;
        float patch[50];
        #pragma unroll
        for (int ic = 0; ic < 2; ic++)
            #pragma unroll
            for (int kh = 0; kh < 5; kh++)
                #pragma unroll
                for (int kw = 0; kw < 5; kw++)
                    patch[ic*25 + kh*5 + kw] = xs[ic*576 + (oh+kh)*24 + ow + kw];

        for (int g = 0; g < 8; g++) {
            float a0=0.f, a1=0.f, a2=0.f, a3=0.f;
            #pragma unroll
            for (int c = 0; c < 50; c++) {
                float4 w = *(const float4*)&w1T[c*32 + g*4];
                a0 = fmaf(patch[c], w.x, a0);
                a1 = fmaf(patch[c], w.y, a1);
                a2 = fmaf(patch[c], w.z, a2);
                a3 = fmaf(patch[c], w.w, a3);
            }
            float av[4] = {a0, a1, a2, a3};
            #pragma unroll
            for (int q = 0; q < 4; q++) {
                int oc = g*4 + q;
                if (oc < 30) {
                    int idx = b*12000 + oc*A1 + p;
                    float v = g_v1[idx] + av[q];
                    float z = (v > VTH1) ? 1.f : 0.f;
                    g_v1[idx] = v * (1.f - z);
                    g_z2[idx] = z;
                    float tt = g_to1[idx];
                    g_to1[idx] = tt - DEC * tt + z;
                }
            }
        }
    }
    // fused maxpool 2x2 + z3 + scaled planar tp2 trace
    __syncthreads();
    for (int e = tid; e < 3000; e += 384) {
        int c = e / 100, q = e % 100;
        int oh = q / 10, ow = q % 10;
        int base = b*12000 + c*A1 + oh*40 + ow*2;
        float m = fmaxf(fmaxf(g_z2[base], g_z2[base+1]),
                        fmaxf(g_z2[base+20], g_z2[base+21]));
        g_z3[b*3000 + e] = m;
        int slot = (size_t)b*PRE2SL + c*PPL + oh*13 + ow;
        float s = g_pre2pA[slot];
        s = s - DEC*s + ETA_P*m;
        g_pre2pA[slot] = s;
        g_pre2pB[slot] = m;
    }
}

// ---------------- K3: conv2 (x10, FFMA2) + IAF + to2 trace + pzA/pzB + z6 + FC/LI readout ----------------
// launch_bounds(600,2): cap regs to 54 so two blocks fit per SM -> single wave (256 blocks <= 296 slots)
__global__ void __launch_bounds__(600, 2) k3_conv2(
                         const float* __restrict__ fc1w, const float* __restrict__ fc1b,
                         const float* __restrict__ outw, float* __restrict__ out, int t) {
    __shared__ float z3s[3000];
    __shared__ float w2s[7500];
    int b = blockIdx.x, tid = threadIdx.x;
    for (int i = tid; i < 3000; i += 600) z3s[i] = g_z3[b*3000 + i];

    int oc = tid % 100, ohh = tid / 100;
    uint64_t accp[3];   // (acc0,acc1),(acc2,acc3),(acc4,acc5)
    accp[0] = 0ull; accp[1] = 0ull; accp[2] = 0ull;

    for (int ic0 = 0; ic0 < 30; ic0 += 3) {
        __syncthreads();
        for (int i = tid; i < 7500; i += 600) {
            int o2 = i / 75, cc = i % 75;
            w2s[i] = g_w2[o2*750 + ic0*25 + cc];
        }
        __syncthreads();
        #pragma unroll
        for (int icl = 0; icl < 3; icl++) {
            const float* zb = &z3s[(ic0 + icl)*100];
            const float* wb = &w2s[oc*75 + icl*25];
            #pragma unroll
            for (int kh = 0; kh < 5; kh++) {
                const float* zrow = &zb[(ohh + kh)*10];
                float r[10];
                #pragma unroll
                for (int u = 0; u < 5; u++) {
                    float2 v = *(const float2*)&zrow[2*u];
                    r[2*u] = v.x; r[2*u+1] = v.y;
                }
                uint64_t rp[9];
                #pragma unroll
                for (int a = 0; a < 9; a++) rp[a] = pack2(r[a], r[a+1]);
                #pragma unroll
                for (int kw = 0; kw < 5; kw++) {
                    float w = wb[kh*5 + kw];
                    uint64_t wd = pack2(w, w);
                    ffma2(accp[0], rp[kw],     wd);
                    ffma2(accp[1], rp[kw + 2], wd);
                    ffma2(accp[2], rp[kw + 4], wd);
                }
            }
        }
    }
    float acc[6];
    unpack2(accp[0], acc[0], acc[1]);
    unpack2(accp[1], acc[2], acc[3]);
    unpack2(accp[2], acc[4], acc[5]);
    // IAF epilogue
    float zmax = 0.f;
    int obase = b*3600 + oc*36 + ohh*6;
    #pragma unroll
    for (int ow = 0; ow < 6; ow++) {
        int idx = obase + ow;
        float v = g_v2[idx] + 10.0f * acc[ow];
        float z = (v > VTH2) ? 1.f : 0.f;
        g_v2[idx] = v * (1.f - z);
        float tt = g_to2[idx];
        float to2n = tt - DEC * tt + z;
        g_to2[idx] = to2n;
        int k = ohh*6 + ow;
        g_pzA[(size_t)b*3600 + k*100 + oc] = z;
        g_pzB[(size_t)b*3600 + k*100 + oc] = -ETA_M * to2n;
        zmax = fmaxf(zmax, z);
    }
    __syncthreads();
    w2s[ohh*100 + oc] = zmax;
    __syncthreads();
    if (tid < 100) {
        float m = 0.f;
        #pragma unroll
        for (int k2 = 0; k2 < 6; k2++) m = fmaxf(m, w2s[k2*100 + tid]);
        w2s[600 + tid] = m;
    }
    __syncthreads();
    if (tid < 50) {
        float a = fc1b[tid];
        const float* wr = &fc1w[tid*100];
        #pragma unroll 4
        for (int k = 0; k < 100; k++) a = fmaf(w2s[600 + k], wr[k], a);
        w2s[700 + tid] = fmaxf(a, 0.f);
    }
    __syncthreads();
    if (tid < 10) {
        int idx = b*10 + tid;
        float iold = g_lii[idx], vold = g_liv[idx];
        float vnew = vold + 0.1f * (iold - vold);
        float a = 0.f;
        const float* wr = &outw[tid*50];
        #pragma unroll
        for (int j = 0; j < 50; j++) a = fmaf(w2s[700 + j], wr[j], a);
        g_liv[idx] = vnew;
        g_lii[idx] = 0.8f * iold + a;
        out[t*2560 + idx] = vnew;
    }
}

// ---------------- K45: fused STDP wgrad (dw1 3j/warp; dw2 FFMA2, planar pre + packed zAB) ----------------
__global__ void __launch_bounds__(320, 2) k45_stdp(const float* __restrict__ x, int t) {
    __shared__ float smem[9632];   // dw2: pts[4096] | pzs[4096] | zAB[1440]; dw1: pre1[2304]
    int bi = blockIdx.x, tid = threadIdx.x;
    int wid = tid >> 5, ti = tid & 31;
    const float* xt = x + (size_t)t * XT;

    if (bi < DW1CH) {
        // ---- dw1: block = 2 batches; warp wid handles j = wid, wid+10, wid+20 ----
        float* pre1 = smem;   // 2*1152 interleaved (tp1*ETA_P, -x*ETA_M)
        int bch = bi;
        int i0 = ti;
        int ib0 = (i0/25)*576 + ((i0%25)/5)*24 + (i0%5);
        bool v1ok = (ti < 18);
        int i1 = ti + 32;
        int ib1 = v1ok ? (i1/25)*576 + ((i1%25)/5)*24 + (i1%5) : 0;

        float a00=0.f,a01=0.f,a10=0.f,a11=0.f,a20=0.f,a21=0.f;
        for (int bb = 0; bb < 2; bb++) {
            int b = bch*2 + bb;
            __syncthreads();
            for (int i2 = tid; i2 < XBC; i2 += 320) {
                pre1[2*i2]   = g_tp1[b*XBC + i2] * ETA_P;
                pre1[2*i2+1] = xt[b*XBC + i2] * (-ETA_M);
            }
            __syncthreads();
            const float* za = &g_z2[b*12000 + wid*400];
            const float* zbp = &g_z2[b*12000 + (wid+10)*400];
            const float* zc = &g_z2[b*12000 + (wid+20)*400];
            const float* ta = &g_to1[b*12000 + wid*400];
            const float* tb = &g_to1[b*12000 + (wid+10)*400];
            const float* tc = &g_to1[b*12000 + (wid+20)*400];

            for (int oh = 0; oh < 20; oh++) {
                int kb = oh*20, ob = oh*24;
                #pragma unroll
                for (int og = 0; og < 5; og++) {
                    float4 z4a = *(const float4*)&za[kb + og*4];
                    float4 z4b = *(const float4*)&zbp[kb + og*4];
                    float4 z4c = *(const float4*)&zc[kb + og*4];
                    float4 t4a = *(const float4*)&ta[kb + og*4];
                    float4 t4b = *(const float4*)&tb[kb + og*4];
                    float4 t4c = *(const float4*)&tc[kb + og*4];
                    const float* zfa = &z4a.x; const float* zfb = &z4b.x; const float* zfc = &z4c.x;
                    const float* tfa = &t4a.x; const float* tfb = &t4b.x; const float* tfc = &t4c.x;
                    #pragma unroll
                    for (int oi = 0; oi < 4; oi++) {
                        int kofs = ob + og*4 + oi;
                        float2 pc0 = *(const float2*)&pre1[2*(ib0 + kofs)];
                        a00 = fmaf(zfa[oi], pc0.x, a00); a00 = fmaf(tfa[oi], pc0.y, a00);
                        a10 = fmaf(zfb[oi], pc0.x, a10); a10 = fmaf(tfb[oi], pc0.y, a10);
                        a20 = fmaf(zfc[oi], pc0.x, a20); a20 = fmaf(tfc[oi], pc0.y, a20);
                        if (v1ok) {
                            float2 pc1 = *(const float2*)&pre1[2*(ib1 + kofs)];
                            a01 = fmaf(zfa[oi], pc1.x, a01); a01 = fmaf(tfa[oi], pc1.y, a01);
                            a11 = fmaf(zfb[oi], pc1.x, a11); a11 = fmaf(tfb[oi], pc1.y, a11);
                            a21 = fmaf(zfc[oi], pc1.x, a21); a21 = fmaf(tfc[oi], pc1.y, a21);
                        }
                    }
                }
            }
        }
        int base = bch*1500;
        g_dw1p[base + wid*50 + i0]      = a00;
        g_dw1p[base + (wid+10)*50 + i0] = a10;
        g_dw1p[base + (wid+20)*50 + i0] = a20;
        if (v1ok) {
            g_dw1p[base + wid*50 + i1]      = a01;
            g_dw1p[base + (wid+10)*50 + i1] = a11;
            g_dw1p[base + (wid+20)*50 + i1] = a21;
        }
    } else {
        // ---- dw2: 5 jtiles(20 j) x 32 bchunks(8 b); FFMA2 packed j-pairs, planar pre ----
        int r = bi - DW1CH;
        int jt = r % 5, bch = r / 5;
        float* pts = smem;            // [4096] planar tp2*ETA_P
        float* pzs = smem + 4096;     // [4096] planar z3
        float* zAB = smem + 8192;     // [1440] = [36 k][10 jpair] float4 (z5_2q, z5_2q+1, o_2q, o_2q+1)
        int iw = wid >> 1, jw = wid & 1;

        int ibase[5];
        bool vm[5];
        #pragma unroll
        for (int m = 0; m < 5; m++) {
            int il = m*32 + ti;
            vm[m] = (il < 150);
            int i = iw*150 + il;
            ibase[m] = (i/25)*PPL + ((i%25)/5)*13 + (i%5);
        }
        uint64_t accp[5][5];   // [jpair q][m]
        #pragma unroll
        for (int q = 0; q < 5; q++)
            #pragma unroll
            for (int m = 0; m < 5; m++) accp[q][m] = 0ull;

        for (int bb = 0; bb < 8; bb++) {
            int b = bch*8 + bb;
            __syncthreads();
            {
                const float4* srcA = (const float4*)&g_pre2pA[(size_t)b*PRE2SL];
                const float4* srcB = (const float4*)&g_pre2pB[(size_t)b*PRE2SL];
                float4* dA = (float4*)pts;
                float4* dB = (float4*)pzs;
                for (int i2 = tid; i2 < 1024; i2 += 320) {
                    dA[i2] = srcA[i2];
                    dB[i2] = srcB[i2];
                }
            }
            {
                const float2* sA = (const float2*)&g_pzA[(size_t)b*3600];
                const float2* sB = (const float2*)&g_pzB[(size_t)b*3600];
                float4* dz = (float4*)zAB;
                for (int i2 = tid; i2 < 360; i2 += 320) {
                    int k = i2 / 10, q = i2 % 10;
                    float2 a = sA[k*50 + jt*10 + q];
                    float2 o = sB[k*50 + jt*10 + q];
                    float4 v; v.x = a.x; v.y = a.y; v.z = o.x; v.w = o.y;
                    dz[k*10 + q] = v;
                }
            }
            __syncthreads();
            for (int oh = 0; oh < 6; oh++) {
                #pragma unroll
                for (int ow = 0; ow < 6; ow++) {
                    int k = oh*6 + ow, kofs = oh*13 + ow;
                    const float4* zl = (const float4*)&zAB[(k*10 + jw*5)*4];
                    uint64_t jz[5], jo[5];
                    #pragma unroll
                    for (int q = 0; q < 5; q++) {
                        float4 v = zl[q];
                        jz[q] = pack2(v.x, v.y);
                        jo[q] = pack2(v.z, v.w);
                    }
                    #pragma unroll
                    for (int m = 0; m < 5; m++) {
                        float pt = pts[ibase[m] + kofs];
                        float pz = pzs[ibase[m] + kofs];
                        uint64_t ptd = pack2(pt, pt);
                        uint64_t pzd = pack2(pz, pz);
                        #pragma unroll
                        for (int q = 0; q < 5; q++) {
                            ffma2(accp[q][m], jz[q], ptd);
                            ffma2(accp[q][m], jo[q], pzd);
                        }
                    }
                }
            }
        }
        size_t pbase = (size_t)bch*75000;
        #pragma unroll
        for (int q = 0; q < 5; q++) {
            int j0 = jt*20 + jw*10 + 2*q;
            float* d0 = &g_dw2p[pbase + j0*750];
            float* d1 = &g_dw2p[pbase + (j0+1)*750];
            #pragma unroll
            for (int m = 0; m < 5; m++) {
                float lo, hi;
                unpack2(accp[q][m], lo, hi);
                if (vm[m]) {
                    int i = iw*150 + m*32 + ti;
                    d0[i] = lo;
                    d1[i] = hi;
                }
            }
        }
    }
}

// ---------------- K6: reduce dw + weight update ----------------
__global__ void k6_finish(void) {
    int bi = blockIdx.x, tid = threadIdx.x;
    if (bi < 293) {
        int c = bi*256 + tid;
        if (c < 75000) {
            float s = 0.f;
            #pragma unroll 8
            for (int ch = 0; ch < DW2CH; ch++) s += g_dw2p[(size_t)ch*75000 + c];
            float w = g_w2[c] + s;
            g_w2[c] = fminf(fmaxf(w, 0.f), 1.f);
        }
    } else {
        int c = (bi - 293)*256 + tid;
        if (c < 1500) {
            float s = 0.f;
            #pragma unroll 8
            for (int ch = 0; ch < DW1CH; ch++) s += g_dw1p[ch*1500 + c];
            float w = g_w1[c] + s;
            g_w1[c] = fminf(fmaxf(w, 0.f), 1.f);
        }
    }
}

// ---------------- launcher ----------------
extern "C" void kernel_launch(void* const* d_in, const int* in_sizes, int n_in,
                              void* d_out, int out_size) {
    const float* x     = (const float*)d_in[0];
    const float* w1    = (const float*)d_in[1];
    const float* w2    = (const float*)d_in[2];
    const float* fc1_w = (const float*)d_in[3];
    const float* fc1_b = (const float*)d_in[4];
    const float* out_w = (const float*)d_in[5];
    float* out = (float*)d_out;

    k_init<<<(L1SZ + 255) / 256, 256>>>(w1, w2);
    for (int t = 0; t < T; t++) {
        k1_conv1<<<B + 36, 384>>>(x, t);
        k3_conv2<<<B, 600>>>(fc1_w, fc1_b, out_w, out, t);
        k45_stdp<<<DW1CH + 5*DW2CH, 320>>>(x, t);
        k6_finish<<<299, 256>>>();
    }
}

// round 17
// speedup vs baseline: 1.6216x; 1.0122x over previous
#include <cuda_runtime.h>
#include <cuda_bf16.h>
#include <cstdint>

// ---------------- constants ----------------
#define B       256
#define T       32
#define XBC     1152        // 2*24*24
#define XT      (B*XBC)
#define A1      400         // 20*20
#define L1SZ    (B*30*A1)   // 3,072,000
#define L2SZ    (B*100*36)  // 921,600
#define DW1CH   128         // 2 batches per chunk
#define DW2CH   32          // 8 batches per chunk

#define VTH1    15.0f
#define VTH2    10.0f
#define DEC     0.02f
#define ETA_P   0.004f
#define ETA_M   0.003f

// padded pre2 layout: plane stride 133 (30 planes -> 3990, pad to 4096 slots/batch)
#define PPL     133
#define PRE2SL  4096

// ---------------- packed fp32x2 helpers (sm_100 FFMA2) ----------------
__device__ __forceinline__ void ffma2(uint64_t& d, uint64_t a, uint64_t b) {
    asm("fma.rn.f32x2 %0, %1, %2, %0;" : "+l"(d) : "l"(a), "l"(b));
}
__device__ __forceinline__ uint64_t pack2(float lo, float hi) {
    uint64_t r; asm("mov.b64 %0, {%1, %2};" : "=l"(r) : "f"(lo), "f"(hi)); return r;
}
__device__ __forceinline__ void unpack2(uint64_t v, float& lo, float& hi) {
    asm("mov.b64 {%0, %1}, %2;" : "=f"(lo), "=f"(hi) : "l"(v));
}

// ---------------- persistent device state ----------------
__device__ float g_w1[1500];
__device__ float g_w2[75000];
__device__ float g_v1[L1SZ];
__device__ float g_v2[L2SZ];
__device__ float g_tp1[XT];
__device__ float g_to1[L1SZ];
__device__ float g_pre2pA[B*PRE2SL];      // planar tp2*ETA_P, padded layout
__device__ float g_pre2pB[B*PRE2SL];      // planar z3, padded layout
__device__ float g_to2[L2SZ];
__device__ float g_z2[L1SZ];
__device__ float g_pzA[B*3600];           // [b][k][j] z5
__device__ float g_pzB[B*3600];           // [b][k][j] -ETA_M*to2
__device__ float g_liv[B*10];
__device__ float g_lii[B*10];
__device__ float g_dw1p[DW1CH*1500];
__device__ float g_dw2p[(size_t)DW2CH*75000];

// ---------------- init ----------------
__global__ void k_init(const float* __restrict__ w1, const float* __restrict__ w2) {
    int i = blockIdx.x * blockDim.x + threadIdx.x;
    if (i < L1SZ) { g_v1[i] = 0.f; g_to1[i] = 0.f; }
    if (i < L2SZ) { g_v2[i] = 0.f; g_to2[i] = 0.f; }
    if (i < XT)   g_tp1[i] = 0.f;
    if (i < B*PRE2SL) { g_pre2pA[i] = 0.f; g_pre2pB[i] = 0.f; }
    if (i < B*10) { g_liv[i] = 0.f; g_lii[i] = 0.f; }
    if (i < 1500)  g_w1[i] = w1[i];
    if (i < 75000) g_w2[i] = w2[i];
}

// ---------------- K13: fused conv1+IAF+traces+pool  ->  conv2+IAF+to2+pz+readout ----------------
// 384 threads, 2 blocks/SM. Blocks >= B do the tp1 trace.
// Phase 2 tiling: 300 active threads = (oc in 0..99) x (oh-pair ohp in 0..2), 12 outputs each.
__global__ void __launch_bounds__(384, 2) k13_fwd(
        const float* __restrict__ x,
        const float* __restrict__ fc1w, const float* __restrict__ fc1b,
        const float* __restrict__ outw, float* __restrict__ out, int t) {
    const float* xt = x + (size_t)t * XT;
    int tid = threadIdx.x;
    if (blockIdx.x >= B) {
        int base = (blockIdx.x - B) * 8192;
        for (int i = tid; i < 8192; i += 384) {
            float tt = g_tp1[base + i];
            g_tp1[base + i] = tt - DEC * tt + xt[base + i];
        }
        return;
    }
    int b = blockIdx.x;
    __shared__ float z3s[3000];
    __shared__ float w2s[7500];   // phase1 alias: [0:1152)=xs, [1152:2752)=w1T
    float* xs  = w2s;
    float* w1T = w2s + 1152;

    for (int i = tid; i < XBC; i += 384) xs[i] = xt[b * XBC + i];
    for (int i = tid; i < 1600; i += 384) {
        int c = i >> 5, oc = i & 31;
        w1T[i] = (oc < 30) ? g_w1[oc * 50 + c] : 0.f;
    }
    __syncthreads();

    // ---- phase 1: conv1 + IAF + to1 trace ----
    for (int p = tid; p < A1; p += 384) {
        int oh = p / 20, ow = p % 20;
        float patch[50];
        #pragma unroll
        for (int ic = 0; ic < 2; ic++)
            #pragma unroll
            for (int kh = 0; kh < 5; kh++)
                #pragma unroll
                for (int kw = 0; kw < 5; kw++)
                    patch[ic*25 + kh*5 + kw] = xs[ic*576 + (oh+kh)*24 + ow + kw];

        for (int g = 0; g < 8; g++) {
            float a0=0.f, a1=0.f, a2=0.f, a3=0.f;
            #pragma unroll
            for (int c = 0; c < 50; c++) {
                float4 w = *(const float4*)&w1T[c*32 + g*4];
                a0 = fmaf(patch[c], w.x, a0);
                a1 = fmaf(patch[c], w.y, a1);
                a2 = fmaf(patch[c], w.z, a2);
                a3 = fmaf(patch[c], w.w, a3);
            }
            float av[4] = {a0, a1, a2, a3};
            #pragma unroll
            for (int q = 0; q < 4; q++) {
                int oc = g*4 + q;
                if (oc < 30) {
                    int idx = b*12000 + oc*A1 + p;
                    float v = g_v1[idx] + av[q];
                    float z = (v > VTH1) ? 1.f : 0.f;
                    g_v1[idx] = v * (1.f - z);
                    g_z2[idx] = z;
                    float tt = g_to1[idx];
                    g_to1[idx] = tt - DEC * tt + z;
                }
            }
        }
    }
    // ---- pool 2x2 -> z3s (smem) + scaled planar tp2 trace ----
    __syncthreads();
    for (int e = tid; e < 3000; e += 384) {
        int c = e / 100, q = e % 100;
        int oh = q / 10, ow = q % 10;
        int base = b*12000 + c*A1 + oh*40 + ow*2;
        float m = fmaxf(fmaxf(g_z2[base], g_z2[base+1]),
                        fmaxf(g_z2[base+20], g_z2[base+21]));
        z3s[e] = m;
        int slot = (size_t)b*PRE2SL + c*PPL + oh*13 + ow;
        float s = g_pre2pA[slot];
        s = s - DEC*s + ETA_P*m;
        g_pre2pA[slot] = s;
        g_pre2pB[slot] = m;
    }

    // ---- phase 2: conv2 (x10, FFMA2), 300 active threads ----
    bool act = (tid < 300);
    int oc = tid % 100, ohp = tid / 100;   // ohp 0..2 (garbage for tid>=300, unused)
    if (!act) { oc = 0; ohp = 0; }
    uint64_t accp[2][3];
    #pragma unroll
    for (int r = 0; r < 2; r++) { accp[r][0]=0ull; accp[r][1]=0ull; accp[r][2]=0ull; }

    for (int ic0 = 0; ic0 < 30; ic0 += 3) {
        __syncthreads();
        for (int i = tid; i < 7500; i += 384) {
            int o2 = i / 75, cc = i % 75;
            w2s[i] = g_w2[o2*750 + ic0*25 + cc];
        }
        __syncthreads();
        if (act) {
            #pragma unroll
            for (int icl = 0; icl < 3; icl++) {
                const float* zb = &z3s[(ic0 + icl)*100];
                const float* wb = &w2s[oc*75 + icl*25];
                #pragma unroll
                for (int r = 0; r < 2; r++) {
                    int ohr = 2*ohp + r;
                    #pragma unroll
                    for (int kh = 0; kh < 5; kh++) {
                        const float* zrow = &zb[(ohr + kh)*10];
                        float rr[10];
                        #pragma unroll
                        for (int u = 0; u < 5; u++) {
                            float2 v = *(const float2*)&zrow[2*u];
                            rr[2*u] = v.x; rr[2*u+1] = v.y;
                        }
                        uint64_t rp[9];
                        #pragma unroll
                        for (int a = 0; a < 9; a++) rp[a] = pack2(rr[a], rr[a+1]);
                        #pragma unroll
                        for (int kw = 0; kw < 5; kw++) {
                            float w = wb[kh*5 + kw];
                            uint64_t wd = pack2(w, w);
                            ffma2(accp[r][0], rp[kw],     wd);
                            ffma2(accp[r][1], rp[kw + 2], wd);
                            ffma2(accp[r][2], rp[kw + 4], wd);
                        }
                    }
                }
            }
        }
    }
    __syncthreads();

    // ---- IAF epilogue + pzA/pzB ----
    float zmax = 0.f;
    if (act) {
        #pragma unroll
        for (int r = 0; r < 2; r++) {
            float acc[6];
            unpack2(accp[r][0], acc[0], acc[1]);
            unpack2(accp[r][1], acc[2], acc[3]);
            unpack2(accp[r][2], acc[4], acc[5]);
            int ohr = 2*ohp + r;
            int obase = b*3600 + oc*36 + ohr*6;
            #pragma unroll
            for (int ow = 0; ow < 6; ow++) {
                int idx = obase + ow;
                float v = g_v2[idx] + 10.0f * acc[ow];
                float z = (v > VTH2) ? 1.f : 0.f;
                g_v2[idx] = v * (1.f - z);
                float tt = g_to2[idx];
                float to2n = tt - DEC * tt + z;
                g_to2[idx] = to2n;
                int k = ohr*6 + ow;
                g_pzA[(size_t)b*3600 + k*100 + oc] = z;
                g_pzB[(size_t)b*3600 + k*100 + oc] = -ETA_M * to2n;
                zmax = fmaxf(zmax, z);
            }
        }
    }
    __syncthreads();
    if (act) w2s[ohp*100 + oc] = zmax;
    __syncthreads();
    if (tid < 100) {
        float m = fmaxf(fmaxf(w2s[tid], w2s[100 + tid]), w2s[200 + tid]);
        w2s[600 + tid] = m;    // z6
    }
    __syncthreads();
    if (tid < 50) {
        float a = fc1b[tid];
        const float* wr = &fc1w[tid*100];
        #pragma unroll 4
        for (int k = 0; k < 100; k++) a = fmaf(w2s[600 + k], wr[k], a);
        w2s[700 + tid] = fmaxf(a, 0.f);
    }
    __syncthreads();
    if (tid < 10) {
        int idx = b*10 + tid;
        float iold = g_lii[idx], vold = g_liv[idx];
        float vnew = vold + 0.1f * (iold - vold);
        float a = 0.f;
        const float* wr = &outw[tid*50];
        #pragma unroll
        for (int j = 0; j < 50; j++) a = fmaf(w2s[700 + j], wr[j], a);
        g_liv[idx] = vnew;
        g_lii[idx] = 0.8f * iold + a;
        out[t*2560 + idx] = vnew;
    }
}

// ---------------- K45: fused STDP wgrad (dw1 3j/warp; dw2 FFMA2, planar pre + packed zAB) ----------------
__global__ void __launch_bounds__(320, 2) k45_stdp(const float* __restrict__ x, int t) {
    __shared__ float smem[9632];   // dw2: pts[4096] | pzs[4096] | zAB[1440]; dw1: pre1[2304]
    int bi = blockIdx.x, tid = threadIdx.x;
    int wid = tid >> 5, ti = tid & 31;
    const float* xt = x + (size_t)t * XT;

    if (bi < DW1CH) {
        // ---- dw1: block = 2 batches; warp wid handles j = wid, wid+10, wid+20 ----
        float* pre1 = smem;   // 2*1152 interleaved (tp1*ETA_P, -x*ETA_M)
        int bch = bi;
        int i0 = ti;
        int ib0 = (i0/25)*576 + ((i0%25)/5)*24 + (i0%5);
        bool v1ok = (ti < 18);
        int i1 = ti + 32;
        int ib1 = v1ok ? (i1/25)*576 + ((i1%25)/5)*24 + (i1%5) : 0;

        float a00=0.f,a01=0.f,a10=0.f,a11=0.f,a20=0.f,a21=0.f;
        for (int bb = 0; bb < 2; bb++) {
            int b = bch*2 + bb;
            __syncthreads();
            for (int i2 = tid; i2 < XBC; i2 += 320) {
                pre1[2*i2]   = g_tp1[b*XBC + i2] * ETA_P;
                pre1[2*i2+1] = xt[b*XBC + i2] * (-ETA_M);
            }
            __syncthreads();
            const float* za = &g_z2[b*12000 + wid*400];
            const float* zbp = &g_z2[b*12000 + (wid+10)*400];
            const float* zc = &g_z2[b*12000 + (wid+20)*400];
            const float* ta = &g_to1[b*12000 + wid*400];
            const float* tb = &g_to1[b*12000 + (wid+10)*400];
            const float* tc = &g_to1[b*12000 + (wid+20)*400];

            for (int oh = 0; oh < 20; oh++) {
                int kb = oh*20, ob = oh*24;
                #pragma unroll
                for (int og = 0; og < 5; og++) {
                    float4 z4a = *(const float4*)&za[kb + og*4];
                    float4 z4b = *(const float4*)&zbp[kb + og*4];
                    float4 z4c = *(const float4*)&zc[kb + og*4];
                    float4 t4a = *(const float4*)&ta[kb + og*4];
                    float4 t4b = *(const float4*)&tb[kb + og*4];
                    float4 t4c = *(const float4*)&tc[kb + og*4];
                    const float* zfa = &z4a.x; const float* zfb = &z4b.x; const float* zfc = &z4c.x;
                    const float* tfa = &t4a.x; const float* tfb = &t4b.x; const float* tfc = &t4c.x;
                    #pragma unroll
                    for (int oi = 0; oi < 4; oi++) {
                        int kofs = ob + og*4 + oi;
                        float2 pc0 = *(const float2*)&pre1[2*(ib0 + kofs)];
                        a00 = fmaf(zfa[oi], pc0.x, a00); a00 = fmaf(tfa[oi], pc0.y, a00);
                        a10 = fmaf(zfb[oi], pc0.x, a10); a10 = fmaf(tfb[oi], pc0.y, a10);
                        a20 = fmaf(zfc[oi], pc0.x, a20); a20 = fmaf(tfc[oi], pc0.y, a20);
                        if (v1ok) {
                            float2 pc1 = *(const float2*)&pre1[2*(ib1 + kofs)];
                            a01 = fmaf(zfa[oi], pc1.x, a01); a01 = fmaf(tfa[oi], pc1.y, a01);
                            a11 = fmaf(zfb[oi], pc1.x, a11); a11 = fmaf(tfb[oi], pc1.y, a11);
                            a21 = fmaf(zfc[oi], pc1.x, a21); a21 = fmaf(tfc[oi], pc1.y, a21);
                        }
                    }
                }
            }
        }
        int base = bch*1500;
        g_dw1p[base + wid*50 + i0]      = a00;
        g_dw1p[base + (wid+10)*50 + i0] = a10;
        g_dw1p[base + (wid+20)*50 + i0] = a20;
        if (v1ok) {
            g_dw1p[base + wid*50 + i1]      = a01;
            g_dw1p[base + (wid+10)*50 + i1] = a11;
            g_dw1p[base + (wid+20)*50 + i1] = a21;
        }
    } else {
        // ---- dw2: 5 jtiles(20 j) x 32 bchunks(8 b); FFMA2 packed j-pairs, planar pre ----
        int r = bi - DW1CH;
        int jt = r % 5, bch = r / 5;
        float* pts = smem;            // [4096] planar tp2*ETA_P
        float* pzs = smem + 4096;     // [4096] planar z3
        float* zAB = smem + 8192;     // [1440] = [36 k][10 jpair] float4 (z5_2q, z5_2q+1, o_2q, o_2q+1)
        int iw = wid >> 1, jw = wid & 1;

        int ibase[5];
        bool vm[5];
        #pragma unroll
        for (int m = 0; m < 5; m++) {
            int il = m*32 + ti;
            vm[m] = (il < 150);
            int i = iw*150 + il;
            ibase[m] = (i/25)*PPL + ((i%25)/5)*13 + (i%5);
        }
        uint64_t accp[5][5];   // [jpair q][m]
        #pragma unroll
        for (int q = 0; q < 5; q++)
            #pragma unroll
            for (int m = 0; m < 5; m++) accp[q][m] = 0ull;

        for (int bb = 0; bb < 8; bb++) {
            int b = bch*8 + bb;
            __syncthreads();
            {
                const float4* srcA = (const float4*)&g_pre2pA[(size_t)b*PRE2SL];
                const float4* srcB = (const float4*)&g_pre2pB[(size_t)b*PRE2SL];
                float4* dA = (float4*)pts;
                float4* dB = (float4*)pzs;
                for (int i2 = tid; i2 < 1024; i2 += 320) {
                    dA[i2] = srcA[i2];
                    dB[i2] = srcB[i2];
                }
            }
            {
                const float2* sA = (const float2*)&g_pzA[(size_t)b*3600];
                const float2* sB = (const float2*)&g_pzB[(size_t)b*3600];
                float4* dz = (float4*)zAB;
                for (int i2 = tid; i2 < 360; i2 += 320) {
                    int k = i2 / 10, q = i2 % 10;
                    float2 a = sA[k*50 + jt*10 + q];
                    float2 o = sB[k*50 + jt*10 + q];
                    float4 v; v.x = a.x; v.y = a.y; v.z = o.x; v.w = o.y;
                    dz[k*10 + q] = v;
                }
            }
            __syncthreads();
            for (int oh = 0; oh < 6; oh++) {
                #pragma unroll
                for (int ow = 0; ow < 6; ow++) {
                    int k = oh*6 + ow, kofs = oh*13 + ow;
                    const float4* zl = (const float4*)&zAB[(k*10 + jw*5)*4];
                    uint64_t jz[5], jo[5];
                    #pragma unroll
                    for (int q = 0; q < 5; q++) {
                        float4 v = zl[q];
                        jz[q] = pack2(v.x, v.y);
                        jo[q] = pack2(v.z, v.w);
                    }
                    #pragma unroll
                    for (int m = 0; m < 5; m++) {
                        float pt = pts[ibase[m] + kofs];
                        float pz = pzs[ibase[m] + kofs];
                        uint64_t ptd = pack2(pt, pt);
                        uint64_t pzd = pack2(pz, pz);
                        #pragma unroll
                        for (int q = 0; q < 5; q++) {
                            ffma2(accp[q][m], jz[q], ptd);
                            ffma2(accp[q][m], jo[q], pzd);
                        }
                    }
                }
            }
        }
        size_t pbase = (size_t)bch*75000;
        #pragma unroll
        for (int q = 0; q < 5; q++) {
            int j0 = jt*20 + jw*10 + 2*q;
            float* d0 = &g_dw2p[pbase + j0*750];
            float* d1 = &g_dw2p[pbase + (j0+1)*750];
            #pragma unroll
            for (int m = 0; m < 5; m++) {
                float lo, hi;
                unpack2(accp[q][m], lo, hi);
                if (vm[m]) {
                    int i = iw*150 + m*32 + ti;
                    d0[i] = lo;
                    d1[i] = hi;
                }
            }
        }
    }
}

// ---------------- K6: reduce dw + weight update ----------------
__global__ void k6_finish(void) {
    int bi = blockIdx.x, tid = threadIdx.x;
    if (bi < 293) {
        int c = bi*256 + tid;
        if (c < 75000) {
            float s = 0.f;
            #pragma unroll 8
            for (int ch = 0; ch < DW2CH; ch++) s += g_dw2p[(size_t)ch*75000 + c];
            float w = g_w2[c] + s;
            g_w2[c] = fminf(fmaxf(w, 0.f), 1.f);
        }
    } else {
        int c = (bi - 293)*256 + tid;
        if (c < 1500) {
            float s = 0.f;
            #pragma unroll 8
            for (int ch = 0; ch < DW1CH; ch++) s += g_dw1p[ch*1500 + c];
            float w = g_w1[c] + s;
            g_w1[c] = fminf(fmaxf(w, 0.f), 1.f);
        }
    }
}

// ---------------- launcher ----------------
extern "C" void kernel_launch(void* const* d_in, const int* in_sizes, int n_in,
                              void* d_out, int out_size) {
    const float* x     = (const float*)d_in[0];
    const float* w1    = (const float*)d_in[1];
    const float* w2    = (const float*)d_in[2];
    const float* fc1_w = (const float*)d_in[3];
    const float* fc1_b = (const float*)d_in[4];
    const float* out_w = (const float*)d_in[5];
    float* out = (float*)d_out;

    k_init<<<(L1SZ + 255) / 256, 256>>>(w1, w2);
    for (int t = 0; t < T; t++) {
        k13_fwd<<<B + 36, 384>>>(x, fc1_w, fc1_b, out_w, out, t);
        k45_stdp<<<DW1CH + 5*DW2CH, 320>>>(x, t);
        k6_finish<<<299, 256>>>();
    }
}